// round 12
// baseline (speedup 1.0000x reference)
#include <cuda_runtime.h>
#include <math.h>

#define HH 512
#define WW 512
#define BB 2
#define HWSZ (HH*WW)
#define NPIX (BB*HWSZ)
#define TOPK 2048
#define CAP 262144
#define NKP (BB*TOPK)
#define NBINS 4096
#define MAXS 32768

#define KXY_OFF  0
#define DESC_OFF (BB*TOPK*2)
#define SC_OFF   (DESC_OFF + BB*TOPK*128)
#define DISP_OFF (SC_OFF + BB*TOPK)

#define CTX 64
#define CTY 32
#define HAL 15
#define BW  96
#define BHT 62
#define NBUF (BHT*BW)

__device__ unsigned long long g_cand[BB*CAP];
__device__ unsigned long long g_surv[BB*MAXS];
__device__ int g_count[BB];
__device__ int g_scount[BB];
__device__ int g_hist[BB*NBINS];
__device__ int g_rank[BB*MAXS];
__device__ int g_selidx[NKP];

__device__ __forceinline__ float4 f4max(float4 a, float4 b) {
    return make_float4(fmaxf(a.x,b.x), fmaxf(a.y,b.y), fmaxf(a.z,b.z), fmaxf(a.w,b.w));
}
// 7-wide horizontal max for 4 outputs at cols g..g+3 from A=[g-4..g-1],B=[g..g+3],C=[g+4..g+7]
__device__ __forceinline__ float4 hmax4(float4 A, float4 B, float4 C) {
    float mB  = fmaxf(fmaxf(B.x,B.y), fmaxf(B.z,B.w));
    float azw = fmaxf(A.z, A.w);
    float cxy = fmaxf(C.x, C.y);
    float4 o;
    o.x = fmaxf(mB, fmaxf(A.y, azw));
    o.y = fmaxf(fmaxf(azw, mB), C.x);
    o.z = fmaxf(A.w, fmaxf(mB, cxy));
    o.w = fmaxf(mB, fmaxf(cxy, C.z));
    return o;
}

// Fully-fused split-half NMS, float4 shared-memory passes.
__global__ __launch_bounds__(512) void nms_k(const float* __restrict__ scores) {
    extern __shared__ float sh[];
    float* S  = sh;
    float* MM = sh + NBUF;
    float* SS = sh + 2*NBUF;
    float* TP = sh + 3*NBUF;

    int tid = threadIdx.x;
    int tx = tid & 31;        // column group (4 cols each)
    int ty = tid >> 5;        // 16 row lanes
    int b   = blockIdx.z;
    int gx0 = blockIdx.x * CTX - HAL;
    int gy0 = blockIdx.y * CTY - HAL;
    int hlo = ((int)(blockIdx.y * CTY) < 256) ? 0 : 256;
    int hhi = hlo + 255;
    const float* sb = scores + b * HWSZ;

    // load scores tile + halo; OOB / cross-half / pad cols -> -inf
    for (int idx = tid; idx < NBUF; idx += 512) {
        int br = idx / BW, bc = idx % BW;
        int gy = gy0 + br, gx = gx0 + bc;
        float v = -INFINITY;
        if (bc < 94 && gy >= hlo && gy <= hhi && gx >= 0 && gx < WW)
            v = sb[gy * WW + gx];
        S[idx] = v;
    }
    __syncthreads();

// vertical 7-max pass: rows [HAL-H, HAL+CTY+H), cols [align4(HAL-H-3), HAL+CTX+H+3)
#define VPASS4(SRC, H)                                                         \
    {                                                                          \
        const int r1 = HAL + CTY + (H);                                        \
        const int c0 = (HAL - (H) - 3) & ~3;                                   \
        const int Gc = (HAL + CTX + (H) + 3 - c0 + 3) >> 2;                    \
        if (tx < Gc) {                                                         \
            int col = c0 + 4*tx;                                               \
            for (int r = HAL - (H) + ty; r < r1; r += 16) {                    \
                const float4* p = (const float4*)(SRC + (r-3)*BW + col);       \
                float4 m = p[0];                                               \
                m = f4max(m, p[24]);  m = f4max(m, p[48]);                     \
                m = f4max(m, p[72]);  m = f4max(m, p[96]);                     \
                m = f4max(m, p[120]); m = f4max(m, p[144]);                    \
                *(float4*)(TP + r*BW + col) = m;                               \
            }                                                                  \
        }                                                                      \
        __syncthreads();                                                       \
    }

#define HLOAD(g, r)                                                            \
    float4 A = *(const float4*)(TP + (r)*BW + (g) - 4);                        \
    float4 B = *(const float4*)(TP + (r)*BW + (g));                            \
    float4 C = *(const float4*)(TP + (r)*BW + (g) + 4);                        \
    float4 o = hmax4(A, B, C);

    // ---- stage 1 (H=12): mm = (s == pool(s)); invalid -> -inf ----
    VPASS4(S, 12)
    {
        const int o0c = 0, Go = (91 - o0c + 3) >> 2;   // cols 0..91
        if (tx < Go) {
            int g = o0c + 4*tx;
            int gxg = gx0 + g;
            for (int r = 3 + ty; r < 59; r += 16) {
                HLOAD(g, r)
                float4 sv = *(const float4*)(S + r*BW + g);
                int gy = gy0 + r;
                bool rok = (gy >= hlo) && (gy <= hhi);
                float4 mm;
                mm.x = (rok && (unsigned)(gxg+0) < 512u) ? ((sv.x==o.x)?1.f:0.f) : -INFINITY;
                mm.y = (rok && (unsigned)(gxg+1) < 512u) ? ((sv.y==o.y)?1.f:0.f) : -INFINITY;
                mm.z = (rok && (unsigned)(gxg+2) < 512u) ? ((sv.z==o.z)?1.f:0.f) : -INFINITY;
                mm.w = (rok && (unsigned)(gxg+3) < 512u) ? ((sv.w==o.w)?1.f:0.f) : -INFINITY;
                *(float4*)(MM + r*BW + g) = mm;
            }
        }
        __syncthreads();
    }

    // ---- iteration 1: supp (H=9), update (H=6) ----
    VPASS4(MM, 9)
    {
        const int o0c = 4, Go = (88 - o0c + 3) >> 2;
        if (tx < Go) {
            int g = o0c + 4*tx;
            int gxg = gx0 + g;
            for (int r = 6 + ty; r < 56; r += 16) {
                HLOAD(g, r)
                float4 sv = *(const float4*)(S + r*BW + g);
                int gy = gy0 + r;
                bool rok = (gy >= hlo) && (gy <= hhi);
                float4 ss;
                ss.x = (rok && (unsigned)(gxg+0) < 512u) ? ((o.x>0.f)?-1.f:sv.x) : -INFINITY;
                ss.y = (rok && (unsigned)(gxg+1) < 512u) ? ((o.y>0.f)?-1.f:sv.y) : -INFINITY;
                ss.z = (rok && (unsigned)(gxg+2) < 512u) ? ((o.z>0.f)?-1.f:sv.z) : -INFINITY;
                ss.w = (rok && (unsigned)(gxg+3) < 512u) ? ((o.w>0.f)?-1.f:sv.w) : -INFINITY;
                *(float4*)(SS + r*BW + g) = ss;
            }
        }
        __syncthreads();
    }
    VPASS4(SS, 6)
    {
        const int o0c = 8, Go = (85 - o0c + 3) >> 2;
        if (tx < Go) {
            int g = o0c + 4*tx;
            for (int r = 9 + ty; r < 53; r += 16) {
                HLOAD(g, r)
                float4 ss = *(const float4*)(SS + r*BW + g);
                float4 mm = *(const float4*)(MM + r*BW + g);
                if (mm.x == 0.f && ss.x >= 0.f && ss.x == o.x) mm.x = 1.f;
                if (mm.y == 0.f && ss.y >= 0.f && ss.y == o.y) mm.y = 1.f;
                if (mm.z == 0.f && ss.z >= 0.f && ss.z == o.z) mm.z = 1.f;
                if (mm.w == 0.f && ss.w >= 0.f && ss.w == o.w) mm.w = 1.f;
                *(float4*)(MM + r*BW + g) = mm;
            }
        }
        __syncthreads();
    }

    // ---- iteration 2: supp (H=3), final (H=0) + compaction ----
    VPASS4(MM, 3)
    {
        const int o0c = 12, Go = (82 - o0c + 3) >> 2;
        if (tx < Go) {
            int g = o0c + 4*tx;
            int gxg = gx0 + g;
            for (int r = 12 + ty; r < 50; r += 16) {
                HLOAD(g, r)
                float4 sv = *(const float4*)(S + r*BW + g);
                int gy = gy0 + r;
                bool rok = (gy >= hlo) && (gy <= hhi);
                float4 ss;
                ss.x = (rok && (unsigned)(gxg+0) < 512u) ? ((o.x>0.f)?-1.f:sv.x) : -INFINITY;
                ss.y = (rok && (unsigned)(gxg+1) < 512u) ? ((o.y>0.f)?-1.f:sv.y) : -INFINITY;
                ss.z = (rok && (unsigned)(gxg+2) < 512u) ? ((o.z>0.f)?-1.f:sv.z) : -INFINITY;
                ss.w = (rok && (unsigned)(gxg+3) < 512u) ? ((o.w>0.f)?-1.f:sv.w) : -INFINITY;
                *(float4*)(SS + r*BW + g) = ss;
            }
        }
        __syncthreads();
    }
    VPASS4(SS, 0)
    {
        const int o0c = 12, Go = (79 - o0c + 3) >> 2;
        if (tx < Go) {
            int g = o0c + 4*tx;
            for (int r = 15 + ty; r < 47; r += 16) {
                HLOAD(g, r)
                float4 ss = *(const float4*)(SS + r*BW + g);
                float4 mm = *(const float4*)(MM + r*BW + g);
                float4 sv = *(const float4*)(S  + r*BW + g);
                int gy = gy0 + r;
#define EMIT(OJ, MJ, SJ, VJ, J)                                                \
                {                                                              \
                    int bc = g + (J);                                          \
                    if (bc >= HAL && bc < HAL + CTX) {                         \
                        float mmv = MJ;                                        \
                        if (mmv == 0.f && SJ >= 0.f && SJ == OJ) mmv = 1.f;    \
                        int gx = gx0 + bc;                                     \
                        int rem = gy * WW + gx;                                \
                        bool border = (gy >= 3) && (gy < 510) &&               \
                                      (gx >= 3) && (gx < 510);                 \
                        float nms = (mmv > 0.f && border) ? VJ : 0.f;          \
                        if (nms > 0.f || rem < TOPK) {                         \
                            int pos = atomicAdd(&g_count[b], 1);               \
                            if (pos < CAP) {                                   \
                                unsigned long long key =                       \
                                    ((unsigned long long)__float_as_uint(nms) << 32) | \
                                    (unsigned long long)(0xFFFFFFFFu - (unsigned)rem); \
                                g_cand[b * CAP + pos] = key;                   \
                                int bin = min(NBINS-1, max(0, (int)(nms * (float)NBINS))); \
                                atomicAdd(&g_hist[b * NBINS + bin], 1);        \
                            }                                                  \
                        }                                                      \
                    }                                                          \
                }
                EMIT(o.x, mm.x, ss.x, sv.x, 0)
                EMIT(o.y, mm.y, ss.y, sv.y, 1)
                EMIT(o.z, mm.z, ss.z, sv.z, 2)
                EMIT(o.w, mm.w, ss.w, sv.w, 3)
            }
        }
    }
}

// per-batch: find threshold bin T (suffix >= TOPK), compact survivors, reset state
__global__ __launch_bounds__(1024) void thresh_compact_k() {
    int b = blockIdx.x;
    int t = threadIdx.x;
    __shared__ int gs[1024];
    __shared__ int sT;
    int base = NBINS - 1 - 4*t;
    int c0 = g_hist[b*NBINS + base];
    int c1 = g_hist[b*NBINS + base-1];
    int c2 = g_hist[b*NBINS + base-2];
    int c3 = g_hist[b*NBINS + base-3];
    int s = c0 + c1 + c2 + c3;
    gs[t] = s;
    g_hist[b*NBINS + base]   = 0;
    g_hist[b*NBINS + base-1] = 0;
    g_hist[b*NBINS + base-2] = 0;
    g_hist[b*NBINS + base-3] = 0;
    __syncthreads();
    for (int off = 1; off < 1024; off <<= 1) {
        int v = (t >= off) ? gs[t-off] : 0;
        __syncthreads();
        gs[t] += v;
        __syncthreads();
    }
    int total = gs[1023];
    int excl = gs[t] - s;
    if (excl < TOPK && excl + s >= TOPK) {
        int T = base - 3;
        int cum = excl + c0;
        if (cum >= TOPK) T = base;
        else { cum += c1; if (cum >= TOPK) T = base-1;
               else { cum += c2; if (cum >= TOPK) T = base-2; } }
        sT = T;
    }
    if (t == 0 && total < TOPK) sT = 0;
    __syncthreads();
    int T = sT;
    int cnt = min(g_count[b], CAP);
    for (int i = t; i < cnt; i += 1024) {
        unsigned long long key = g_cand[b*CAP + i];
        float v = __uint_as_float((unsigned)(key >> 32));
        int bin = min(NBINS-1, max(0, (int)(v * (float)NBINS)));
        if (bin >= T) {
            int p = atomicAdd(&g_scount[b], 1);
            if (p < MAXS) g_surv[b*MAXS + p] = key;
        }
    }
    __syncthreads();
    if (t == 0) g_count[b] = 0;
}

// 2D-parallel partial ranking
__global__ __launch_bounds__(256) void rank_part_k() {
    int b = blockIdx.z;
    int m = min(g_scount[b], MAXS);
    const unsigned long long* sv = g_surv + b*MAXS;
    __shared__ unsigned long long sk[256];
    for (int ib = blockIdx.y; ib * 256 < m; ib += gridDim.y) {
        int i = ib * 256 + threadIdx.x;
        unsigned long long mykey = (i < m) ? sv[i] : 0ull;
        for (int jt = blockIdx.x; jt * 256 < m; jt += gridDim.x) {
            int j = jt * 256 + threadIdx.x;
            sk[threadIdx.x] = (j < m) ? sv[j] : 0ull;
            __syncthreads();
            int lim = min(256, m - jt * 256);
            int r = 0;
            if (i < m) {
                int u = 0;
                for (; u + 4 <= lim; u += 4) {
                    r += (sk[u]   > mykey) ? 1 : 0;
                    r += (sk[u+1] > mykey) ? 1 : 0;
                    r += (sk[u+2] > mykey) ? 1 : 0;
                    r += (sk[u+3] > mykey) ? 1 : 0;
                }
                for (; u < lim; ++u) r += (sk[u] > mykey) ? 1 : 0;
            }
            if (i < m && r) atomicAdd(&g_rank[b*MAXS + i], r);
            __syncthreads();
        }
    }
}

// scatter rank -> selidx slot; self-reset g_rank
__global__ __launch_bounds__(256) void scatter_k() {
    int b = blockIdx.y;
    int m = min(g_scount[b], MAXS);
    for (int i = blockIdx.x * 256 + threadIdx.x; i < m; i += gridDim.x * 256) {
        int r = g_rank[b*MAXS + i];
        g_rank[b*MAXS + i] = 0;
        if (r < TOPK) {
            unsigned long long key = g_surv[b*MAXS + i];
            int flatidx = (int)(0xFFFFFFFFu - (unsigned)(key & 0xFFFFFFFFull));
            g_selidx[b * TOPK + r] = flatidx;
        }
    }
}

__device__ __forceinline__ float bilin1(const float* base, float x, float y) {
    float x0f = floorf(x), y0f = floorf(y);
    float wx = x - x0f, wy = y - y0f;
    int x0 = min(max((int)x0f, 0), WW - 1);
    int x1 = min(max((int)x0f + 1, 0), WW - 1);
    int y0 = min(max((int)y0f, 0), HH - 1);
    int y1 = min(max((int)y0f + 1, 0), HH - 1);
    float v00 = base[y0 * WW + x0], v01 = base[y0 * WW + x1];
    float v10 = base[y1 * WW + x0], v11 = base[y1 * WW + x1];
    return v00 * (1.f - wx) * (1.f - wy) + v01 * wx * (1.f - wy)
         + v10 * (1.f - wx) * wy + v11 * wx * wy;
}

// fused: warp0 does 5x5 softmax refine; all 128 threads sample+normalize desc
__global__ __launch_bounds__(128) void refine_desc_k(const float* __restrict__ scores,
                                                     const float* __restrict__ dmap,
                                                     float* __restrict__ out) {
    int t = blockIdx.x;
    int c = threadIdx.x;
    int b = t >> 11;
    int w = c >> 5, lane = c & 31;
    __shared__ float sxy[2];

    if (t == 0 && c < BB) g_scount[c] = 0;

    if (w == 0) {
        int idx = g_selidx[t];
        int ky = idx >> 9, kx = idx & 511;
        const float* sb = scores + b * HWSZ;
        int p = lane;
        float dxf = 0.f, dyf = 0.f, v = 0.f;
        if (p < 25) {
            int dy = p / 5 - 2, dx = p % 5 - 2;
            dxf = (float)dx; dyf = (float)dy;
            int y = ky + dy, x = kx + dx;
            v = (y >= 0 && y < HH && x >= 0 && x < WW) ? sb[y * WW + x] : 0.0f;
        }
        float pv = (p < 25) ? v : -INFINITY;
#pragma unroll
        for (int o = 16; o > 0; o >>= 1) pv = fmaxf(pv, __shfl_xor_sync(0xFFFFFFFFu, pv, o));
        float e = (p < 25) ? expf((v - pv) * 10.0f) : 0.0f;
        float se = e, sxv = e * dxf, syv = e * dyf;
#pragma unroll
        for (int o = 16; o > 0; o >>= 1) {
            se  += __shfl_xor_sync(0xFFFFFFFFu, se, o);
            sxv += __shfl_xor_sync(0xFFFFFFFFu, sxv, o);
            syv += __shfl_xor_sync(0xFFFFFFFFu, syv, o);
        }
        float rx = sxv / se, ry = syv / se;
        float ddx = (dxf - rx) * 0.5f, ddy = (dyf - ry) * 0.5f;
        float dc = e * (ddx * ddx + ddy * ddy);
#pragma unroll
        for (int o = 16; o > 0; o >>= 1) dc += __shfl_xor_sync(0xFFFFFFFFu, dc, o);

        if (lane == 0) {
            float kxf = ((float)kx + rx) / 511.f * 2.f - 1.f;
            float kyf = ((float)ky + ry) / 511.f * 2.f - 1.f;
            out[KXY_OFF + t * 2 + 0] = kxf;
            out[KXY_OFF + t * 2 + 1] = kyf;
            out[DISP_OFF + t] = dc / se;
            float xs = (kxf + 1.f) * 0.5f * (WW - 1);
            float ys = (kyf + 1.f) * 0.5f * (HH - 1);
            out[SC_OFF + t] = bilin1(sb, xs, ys);
            sxy[0] = xs; sxy[1] = ys;
        }
    }
    __syncthreads();

    float x = sxy[0], y = sxy[1];
    float x0f = floorf(x), y0f = floorf(y);
    float wx = x - x0f, wy = y - y0f;
    int x0 = min(max((int)x0f, 0), WW - 1);
    int x1 = min(max((int)x0f + 1, 0), WW - 1);
    int y0 = min(max((int)y0f, 0), HH - 1);
    int y1 = min(max((int)y0f + 1, 0), HH - 1);
    const float* base = dmap + ((size_t)b * 128 + c) * HWSZ;
    float v00 = base[y0 * WW + x0], v01 = base[y0 * WW + x1];
    float v10 = base[y1 * WW + x0], v11 = base[y1 * WW + x1];
    float v = v00 * (1.f - wx) * (1.f - wy) + v01 * wx * (1.f - wy)
            + v10 * (1.f - wx) * wy + v11 * wx * wy;

    float sq = v * v;
#pragma unroll
    for (int o = 16; o > 0; o >>= 1) sq += __shfl_xor_sync(0xFFFFFFFFu, sq, o);
    __shared__ float wsum[4];
    if (lane == 0) wsum[w] = sq;
    __syncthreads();
    float tot = wsum[0] + wsum[1] + wsum[2] + wsum[3];
    float nrm = fmaxf(sqrtf(tot), 1e-12f);
    out[DESC_OFF + (size_t)t * 128 + c] = v / nrm;
}

extern "C" void kernel_launch(void* const* d_in, const int* in_sizes, int n_in,
                              void* d_out, int out_size) {
    const float* scores;
    const float* dmap;
    if (in_sizes[0] == NPIX) {
        scores = (const float*)d_in[0];
        dmap   = (const float*)d_in[1];
    } else {
        scores = (const float*)d_in[1];
        dmap   = (const float*)d_in[0];
    }
    float* out = (float*)d_out;

    static bool attr_done = false;
    if (!attr_done) {
        cudaFuncSetAttribute(nms_k, cudaFuncAttributeMaxDynamicSharedMemorySize,
                             (4 * NBUF + 64) * (int)sizeof(float));
        attr_done = true;
    }

    dim3 ng(WW / CTX, HH / CTY, BB);
    nms_k<<<ng, 512, (4 * NBUF + 64) * sizeof(float)>>>(scores);

    thresh_compact_k<<<BB, 1024>>>();

    dim3 rg(8, 8, BB);
    rank_part_k<<<rg, 256>>>();

    dim3 sg(16, BB);
    scatter_k<<<sg, 256>>>();

    refine_desc_k<<<NKP, 128>>>(scores, dmap, out);
}

// round 13
// speedup vs baseline: 1.0614x; 1.0614x over previous
#include <cuda_runtime.h>
#include <math.h>

#define HH 512
#define WW 512
#define BB 2
#define HWSZ (HH*WW)
#define NPIX (BB*HWSZ)
#define TOPK 2048
#define CAP 262144
#define NKP (BB*TOPK)
#define NBINS 4096
#define MAXS 32768

#define KXY_OFF  0
#define DESC_OFF (BB*TOPK*2)
#define SC_OFF   (DESC_OFF + BB*TOPK*128)
#define DISP_OFF (SC_OFF + BB*TOPK)

#define CTX 64
#define CTY 32
#define HAL 15
#define BW  96
#define BHT 62
#define NBUF (BHT*BW)
#define NMS_T 1024

__device__ unsigned long long g_cand[BB*CAP];
__device__ unsigned long long g_surv[BB*MAXS];
__device__ int g_count[BB];
__device__ int g_scount[BB];
__device__ int g_hist[BB*NBINS];
__device__ int g_rank[BB*MAXS];
__device__ int g_selidx[NKP];

__device__ __forceinline__ float4 f4max(float4 a, float4 b) {
    return make_float4(fmaxf(a.x,b.x), fmaxf(a.y,b.y), fmaxf(a.z,b.z), fmaxf(a.w,b.w));
}
// 7-wide horizontal max for 4 outputs at cols g..g+3 from A=[g-4..g-1],B=[g..g+3],C=[g+4..g+7]
__device__ __forceinline__ float4 hmax4(float4 A, float4 B, float4 C) {
    float mB  = fmaxf(fmaxf(B.x,B.y), fmaxf(B.z,B.w));
    float azw = fmaxf(A.z, A.w);
    float cxy = fmaxf(C.x, C.y);
    float4 o;
    o.x = fmaxf(mB, fmaxf(A.y, azw));
    o.y = fmaxf(fmaxf(azw, mB), C.x);
    o.z = fmaxf(A.w, fmaxf(mB, cxy));
    o.w = fmaxf(mB, fmaxf(cxy, C.z));
    return o;
}

// Fully-fused split-half NMS, float4 shared-memory passes, 1024 threads.
__global__ __launch_bounds__(NMS_T) void nms_k(const float* __restrict__ scores) {
    extern __shared__ float sh[];
    float* S  = sh;
    float* MM = sh + NBUF;
    float* SS = sh + 2*NBUF;
    float* TP = sh + 3*NBUF;

    int tid = threadIdx.x;
    int tx = tid & 31;        // column group (4 cols each)
    int ty = tid >> 5;        // 32 row lanes
    int b   = blockIdx.z;
    int gx0 = blockIdx.x * CTX - HAL;
    int gy0 = blockIdx.y * CTY - HAL;
    int hlo = ((int)(blockIdx.y * CTY) < 256) ? 0 : 256;
    int hhi = hlo + 255;
    const float* sb = scores + b * HWSZ;

    // load scores tile + halo; OOB / cross-half / pad cols -> -inf
    for (int idx = tid; idx < NBUF; idx += NMS_T) {
        int br = idx / BW, bc = idx % BW;
        int gy = gy0 + br, gx = gx0 + bc;
        float v = -INFINITY;
        if (bc < 94 && gy >= hlo && gy <= hhi && gx >= 0 && gx < WW)
            v = sb[gy * WW + gx];
        S[idx] = v;
    }
    __syncthreads();

// vertical 7-max pass: rows [HAL-H, HAL+CTY+H), cols [align4(HAL-H-3), HAL+CTX+H+3)
#define VPASS4(SRC, H)                                                         \
    {                                                                          \
        const int r1 = HAL + CTY + (H);                                        \
        const int c0 = (HAL - (H) - 3) & ~3;                                   \
        const int Gc = (HAL + CTX + (H) + 3 - c0 + 3) >> 2;                    \
        if (tx < Gc) {                                                         \
            int col = c0 + 4*tx;                                               \
            for (int r = HAL - (H) + ty; r < r1; r += 32) {                    \
                const float4* p = (const float4*)(SRC + (r-3)*BW + col);       \
                float4 m = p[0];                                               \
                m = f4max(m, p[24]);  m = f4max(m, p[48]);                     \
                m = f4max(m, p[72]);  m = f4max(m, p[96]);                     \
                m = f4max(m, p[120]); m = f4max(m, p[144]);                    \
                *(float4*)(TP + r*BW + col) = m;                               \
            }                                                                  \
        }                                                                      \
        __syncthreads();                                                       \
    }

#define HLOAD(g, r)                                                            \
    float4 A = *(const float4*)(TP + (r)*BW + (g) - 4);                        \
    float4 B = *(const float4*)(TP + (r)*BW + (g));                            \
    float4 C = *(const float4*)(TP + (r)*BW + (g) + 4);                        \
    float4 o = hmax4(A, B, C);

    // ---- stage 1 (H=12): mm = (s == pool(s)); invalid -> -inf ----
    VPASS4(S, 12)
    {
        const int o0c = 0, Go = (91 - o0c + 3) >> 2;   // cols 0..91
        if (tx < Go) {
            int g = o0c + 4*tx;
            int gxg = gx0 + g;
            for (int r = 3 + ty; r < 59; r += 32) {
                HLOAD(g, r)
                float4 sv = *(const float4*)(S + r*BW + g);
                int gy = gy0 + r;
                bool rok = (gy >= hlo) && (gy <= hhi);
                float4 mm;
                mm.x = (rok && (unsigned)(gxg+0) < 512u) ? ((sv.x==o.x)?1.f:0.f) : -INFINITY;
                mm.y = (rok && (unsigned)(gxg+1) < 512u) ? ((sv.y==o.y)?1.f:0.f) : -INFINITY;
                mm.z = (rok && (unsigned)(gxg+2) < 512u) ? ((sv.z==o.z)?1.f:0.f) : -INFINITY;
                mm.w = (rok && (unsigned)(gxg+3) < 512u) ? ((sv.w==o.w)?1.f:0.f) : -INFINITY;
                *(float4*)(MM + r*BW + g) = mm;
            }
        }
        __syncthreads();
    }

    // ---- iteration 1: supp (H=9), update (H=6) ----
    VPASS4(MM, 9)
    {
        const int o0c = 4, Go = (88 - o0c + 3) >> 2;
        if (tx < Go) {
            int g = o0c + 4*tx;
            int gxg = gx0 + g;
            for (int r = 6 + ty; r < 56; r += 32) {
                HLOAD(g, r)
                float4 sv = *(const float4*)(S + r*BW + g);
                int gy = gy0 + r;
                bool rok = (gy >= hlo) && (gy <= hhi);
                float4 ss;
                ss.x = (rok && (unsigned)(gxg+0) < 512u) ? ((o.x>0.f)?-1.f:sv.x) : -INFINITY;
                ss.y = (rok && (unsigned)(gxg+1) < 512u) ? ((o.y>0.f)?-1.f:sv.y) : -INFINITY;
                ss.z = (rok && (unsigned)(gxg+2) < 512u) ? ((o.z>0.f)?-1.f:sv.z) : -INFINITY;
                ss.w = (rok && (unsigned)(gxg+3) < 512u) ? ((o.w>0.f)?-1.f:sv.w) : -INFINITY;
                *(float4*)(SS + r*BW + g) = ss;
            }
        }
        __syncthreads();
    }
    VPASS4(SS, 6)
    {
        const int o0c = 8, Go = (85 - o0c + 3) >> 2;
        if (tx < Go) {
            int g = o0c + 4*tx;
            for (int r = 9 + ty; r < 53; r += 32) {
                HLOAD(g, r)
                float4 ss = *(const float4*)(SS + r*BW + g);
                float4 mm = *(const float4*)(MM + r*BW + g);
                if (mm.x == 0.f && ss.x >= 0.f && ss.x == o.x) mm.x = 1.f;
                if (mm.y == 0.f && ss.y >= 0.f && ss.y == o.y) mm.y = 1.f;
                if (mm.z == 0.f && ss.z >= 0.f && ss.z == o.z) mm.z = 1.f;
                if (mm.w == 0.f && ss.w >= 0.f && ss.w == o.w) mm.w = 1.f;
                *(float4*)(MM + r*BW + g) = mm;
            }
        }
        __syncthreads();
    }

    // ---- iteration 2: supp (H=3), final (H=0) + compaction ----
    VPASS4(MM, 3)
    {
        const int o0c = 12, Go = (82 - o0c + 3) >> 2;
        if (tx < Go) {
            int g = o0c + 4*tx;
            int gxg = gx0 + g;
            for (int r = 12 + ty; r < 50; r += 32) {
                HLOAD(g, r)
                float4 sv = *(const float4*)(S + r*BW + g);
                int gy = gy0 + r;
                bool rok = (gy >= hlo) && (gy <= hhi);
                float4 ss;
                ss.x = (rok && (unsigned)(gxg+0) < 512u) ? ((o.x>0.f)?-1.f:sv.x) : -INFINITY;
                ss.y = (rok && (unsigned)(gxg+1) < 512u) ? ((o.y>0.f)?-1.f:sv.y) : -INFINITY;
                ss.z = (rok && (unsigned)(gxg+2) < 512u) ? ((o.z>0.f)?-1.f:sv.z) : -INFINITY;
                ss.w = (rok && (unsigned)(gxg+3) < 512u) ? ((o.w>0.f)?-1.f:sv.w) : -INFINITY;
                *(float4*)(SS + r*BW + g) = ss;
            }
        }
        __syncthreads();
    }
    VPASS4(SS, 0)
    {
        const int o0c = 12, Go = (79 - o0c + 3) >> 2;
        if (tx < Go) {
            int g = o0c + 4*tx;
            for (int r = 15 + ty; r < 47; r += 32) {
                HLOAD(g, r)
                float4 ss = *(const float4*)(SS + r*BW + g);
                float4 mm = *(const float4*)(MM + r*BW + g);
                float4 sv = *(const float4*)(S  + r*BW + g);
                int gy = gy0 + r;
#define EMIT(OJ, MJ, SJ, VJ, J)                                                \
                {                                                              \
                    int bc = g + (J);                                          \
                    if (bc >= HAL && bc < HAL + CTX) {                         \
                        float mmv = MJ;                                        \
                        if (mmv == 0.f && SJ >= 0.f && SJ == OJ) mmv = 1.f;    \
                        int gx = gx0 + bc;                                     \
                        int rem = gy * WW + gx;                                \
                        bool border = (gy >= 3) && (gy < 510) &&               \
                                      (gx >= 3) && (gx < 510);                 \
                        float nms = (mmv > 0.f && border) ? VJ : 0.f;          \
                        if (nms > 0.f || rem < TOPK) {                         \
                            int pos = atomicAdd(&g_count[b], 1);               \
                            if (pos < CAP) {                                   \
                                unsigned long long key =                       \
                                    ((unsigned long long)__float_as_uint(nms) << 32) | \
                                    (unsigned long long)(0xFFFFFFFFu - (unsigned)rem); \
                                g_cand[b * CAP + pos] = key;                   \
                                int bin = min(NBINS-1, max(0, (int)(nms * (float)NBINS))); \
                                atomicAdd(&g_hist[b * NBINS + bin], 1);        \
                            }                                                  \
                        }                                                      \
                    }                                                          \
                }
                EMIT(o.x, mm.x, ss.x, sv.x, 0)
                EMIT(o.y, mm.y, ss.y, sv.y, 1)
                EMIT(o.z, mm.z, ss.z, sv.z, 2)
                EMIT(o.w, mm.w, ss.w, sv.w, 3)
            }
        }
    }
}

// per-batch: find threshold bin T (suffix >= TOPK), compact survivors, reset state
__global__ __launch_bounds__(1024) void thresh_compact_k() {
    int b = blockIdx.x;
    int t = threadIdx.x;
    __shared__ int gs[1024];
    __shared__ int sT;
    int base = NBINS - 1 - 4*t;
    int c0 = g_hist[b*NBINS + base];
    int c1 = g_hist[b*NBINS + base-1];
    int c2 = g_hist[b*NBINS + base-2];
    int c3 = g_hist[b*NBINS + base-3];
    int s = c0 + c1 + c2 + c3;
    gs[t] = s;
    g_hist[b*NBINS + base]   = 0;
    g_hist[b*NBINS + base-1] = 0;
    g_hist[b*NBINS + base-2] = 0;
    g_hist[b*NBINS + base-3] = 0;
    __syncthreads();
    for (int off = 1; off < 1024; off <<= 1) {
        int v = (t >= off) ? gs[t-off] : 0;
        __syncthreads();
        gs[t] += v;
        __syncthreads();
    }
    int total = gs[1023];
    int excl = gs[t] - s;
    if (excl < TOPK && excl + s >= TOPK) {
        int T = base - 3;
        int cum = excl + c0;
        if (cum >= TOPK) T = base;
        else { cum += c1; if (cum >= TOPK) T = base-1;
               else { cum += c2; if (cum >= TOPK) T = base-2; } }
        sT = T;
    }
    if (t == 0 && total < TOPK) sT = 0;
    __syncthreads();
    int T = sT;
    int cnt = min(g_count[b], CAP);
    for (int i = t; i < cnt; i += 1024) {
        unsigned long long key = g_cand[b*CAP + i];
        float v = __uint_as_float((unsigned)(key >> 32));
        int bin = min(NBINS-1, max(0, (int)(v * (float)NBINS)));
        if (bin >= T) {
            int p = atomicAdd(&g_scount[b], 1);
            if (p < MAXS) g_surv[b*MAXS + p] = key;
        }
    }
    __syncthreads();
    if (t == 0) g_count[b] = 0;
}

// 2D-parallel partial ranking
__global__ __launch_bounds__(256) void rank_part_k() {
    int b = blockIdx.z;
    int m = min(g_scount[b], MAXS);
    const unsigned long long* sv = g_surv + b*MAXS;
    __shared__ unsigned long long sk[256];
    for (int ib = blockIdx.y; ib * 256 < m; ib += gridDim.y) {
        int i = ib * 256 + threadIdx.x;
        unsigned long long mykey = (i < m) ? sv[i] : 0ull;
        for (int jt = blockIdx.x; jt * 256 < m; jt += gridDim.x) {
            int j = jt * 256 + threadIdx.x;
            sk[threadIdx.x] = (j < m) ? sv[j] : 0ull;
            __syncthreads();
            int lim = min(256, m - jt * 256);
            int r = 0;
            if (i < m) {
                int u = 0;
                for (; u + 4 <= lim; u += 4) {
                    r += (sk[u]   > mykey) ? 1 : 0;
                    r += (sk[u+1] > mykey) ? 1 : 0;
                    r += (sk[u+2] > mykey) ? 1 : 0;
                    r += (sk[u+3] > mykey) ? 1 : 0;
                }
                for (; u < lim; ++u) r += (sk[u] > mykey) ? 1 : 0;
            }
            if (i < m && r) atomicAdd(&g_rank[b*MAXS + i], r);
            __syncthreads();
        }
    }
}

// scatter rank -> selidx slot; self-reset g_rank
__global__ __launch_bounds__(256) void scatter_k() {
    int b = blockIdx.y;
    int m = min(g_scount[b], MAXS);
    for (int i = blockIdx.x * 256 + threadIdx.x; i < m; i += gridDim.x * 256) {
        int r = g_rank[b*MAXS + i];
        g_rank[b*MAXS + i] = 0;
        if (r < TOPK) {
            unsigned long long key = g_surv[b*MAXS + i];
            int flatidx = (int)(0xFFFFFFFFu - (unsigned)(key & 0xFFFFFFFFull));
            g_selidx[b * TOPK + r] = flatidx;
        }
    }
}

__device__ __forceinline__ float bilin1(const float* base, float x, float y) {
    float x0f = floorf(x), y0f = floorf(y);
    float wx = x - x0f, wy = y - y0f;
    int x0 = min(max((int)x0f, 0), WW - 1);
    int x1 = min(max((int)x0f + 1, 0), WW - 1);
    int y0 = min(max((int)y0f, 0), HH - 1);
    int y1 = min(max((int)y0f + 1, 0), HH - 1);
    float v00 = base[y0 * WW + x0], v01 = base[y0 * WW + x1];
    float v10 = base[y1 * WW + x0], v11 = base[y1 * WW + x1];
    return v00 * (1.f - wx) * (1.f - wy) + v01 * wx * (1.f - wy)
         + v10 * (1.f - wx) * wy + v11 * wx * wy;
}

// fused: warp0 does 5x5 softmax refine; all 128 threads sample+normalize desc
__global__ __launch_bounds__(128) void refine_desc_k(const float* __restrict__ scores,
                                                     const float* __restrict__ dmap,
                                                     float* __restrict__ out) {
    int t = blockIdx.x;
    int c = threadIdx.x;
    int b = t >> 11;
    int w = c >> 5, lane = c & 31;
    __shared__ float sxy[2];

    if (t == 0 && c < BB) g_scount[c] = 0;

    if (w == 0) {
        int idx = g_selidx[t];
        int ky = idx >> 9, kx = idx & 511;
        const float* sb = scores + b * HWSZ;
        int p = lane;
        float dxf = 0.f, dyf = 0.f, v = 0.f;
        if (p < 25) {
            int dy = p / 5 - 2, dx = p % 5 - 2;
            dxf = (float)dx; dyf = (float)dy;
            int y = ky + dy, x = kx + dx;
            v = (y >= 0 && y < HH && x >= 0 && x < WW) ? sb[y * WW + x] : 0.0f;
        }
        float pv = (p < 25) ? v : -INFINITY;
#pragma unroll
        for (int o = 16; o > 0; o >>= 1) pv = fmaxf(pv, __shfl_xor_sync(0xFFFFFFFFu, pv, o));
        float e = (p < 25) ? expf((v - pv) * 10.0f) : 0.0f;
        float se = e, sxv = e * dxf, syv = e * dyf;
#pragma unroll
        for (int o = 16; o > 0; o >>= 1) {
            se  += __shfl_xor_sync(0xFFFFFFFFu, se, o);
            sxv += __shfl_xor_sync(0xFFFFFFFFu, sxv, o);
            syv += __shfl_xor_sync(0xFFFFFFFFu, syv, o);
        }
        float rx = sxv / se, ry = syv / se;
        float ddx = (dxf - rx) * 0.5f, ddy = (dyf - ry) * 0.5f;
        float dc = e * (ddx * ddx + ddy * ddy);
#pragma unroll
        for (int o = 16; o > 0; o >>= 1) dc += __shfl_xor_sync(0xFFFFFFFFu, dc, o);

        if (lane == 0) {
            float kxf = ((float)kx + rx) / 511.f * 2.f - 1.f;
            float kyf = ((float)ky + ry) / 511.f * 2.f - 1.f;
            out[KXY_OFF + t * 2 + 0] = kxf;
            out[KXY_OFF + t * 2 + 1] = kyf;
            out[DISP_OFF + t] = dc / se;
            float xs = (kxf + 1.f) * 0.5f * (WW - 1);
            float ys = (kyf + 1.f) * 0.5f * (HH - 1);
            out[SC_OFF + t] = bilin1(sb, xs, ys);
            sxy[0] = xs; sxy[1] = ys;
        }
    }
    __syncthreads();

    float x = sxy[0], y = sxy[1];
    float x0f = floorf(x), y0f = floorf(y);
    float wx = x - x0f, wy = y - y0f;
    int x0 = min(max((int)x0f, 0), WW - 1);
    int x1 = min(max((int)x0f + 1, 0), WW - 1);
    int y0 = min(max((int)y0f, 0), HH - 1);
    int y1 = min(max((int)y0f + 1, 0), HH - 1);
    const float* base = dmap + ((size_t)b * 128 + c) * HWSZ;
    float v00 = base[y0 * WW + x0], v01 = base[y0 * WW + x1];
    float v10 = base[y1 * WW + x0], v11 = base[y1 * WW + x1];
    float v = v00 * (1.f - wx) * (1.f - wy) + v01 * wx * (1.f - wy)
            + v10 * (1.f - wx) * wy + v11 * wx * wy;

    float sq = v * v;
#pragma unroll
    for (int o = 16; o > 0; o >>= 1) sq += __shfl_xor_sync(0xFFFFFFFFu, sq, o);
    __shared__ float wsum[4];
    if (lane == 0) wsum[w] = sq;
    __syncthreads();
    float tot = wsum[0] + wsum[1] + wsum[2] + wsum[3];
    float nrm = fmaxf(sqrtf(tot), 1e-12f);
    out[DESC_OFF + (size_t)t * 128 + c] = v / nrm;
}

extern "C" void kernel_launch(void* const* d_in, const int* in_sizes, int n_in,
                              void* d_out, int out_size) {
    const float* scores;
    const float* dmap;
    if (in_sizes[0] == NPIX) {
        scores = (const float*)d_in[0];
        dmap   = (const float*)d_in[1];
    } else {
        scores = (const float*)d_in[1];
        dmap   = (const float*)d_in[0];
    }
    float* out = (float*)d_out;

    static bool attr_done = false;
    if (!attr_done) {
        cudaFuncSetAttribute(nms_k, cudaFuncAttributeMaxDynamicSharedMemorySize,
                             (4 * NBUF + 64) * (int)sizeof(float));
        attr_done = true;
    }

    dim3 ng(WW / CTX, HH / CTY, BB);
    nms_k<<<ng, NMS_T, (4 * NBUF + 64) * sizeof(float)>>>(scores);

    thresh_compact_k<<<BB, 1024>>>();

    dim3 rg(8, 8, BB);
    rank_part_k<<<rg, 256>>>();

    dim3 sg(16, BB);
    scatter_k<<<sg, 256>>>();

    refine_desc_k<<<NKP, 128>>>(scores, dmap, out);
}

// round 14
// speedup vs baseline: 1.0728x; 1.0108x over previous
#include <cuda_runtime.h>
#include <math.h>

#define HH 512
#define WW 512
#define BB 2
#define HWSZ (HH*WW)
#define NPIX (BB*HWSZ)
#define TOPK 2048
#define CAP 262144
#define NKP (BB*TOPK)
#define NBINS 4096
#define MAXS 32768

#define KXY_OFF  0
#define DESC_OFF (BB*TOPK*2)
#define SC_OFF   (DESC_OFF + BB*TOPK*128)
#define DISP_OFF (SC_OFF + BB*TOPK)

#define CTX 64
#define CTY 32
#define HAL 15
#define BW  96
#define BHT 62
#define NBUF (BHT*BW)
#define NMS_T 1024

__device__ unsigned long long g_cand[BB*CAP];
__device__ unsigned long long g_surv[BB*MAXS];
__device__ int g_count[BB];
__device__ int g_scount[BB];
__device__ int g_hist[BB*NBINS];
__device__ int g_rank[BB*MAXS];
__device__ int g_rowdone[BB*128];
__device__ int g_selidx[NKP];

__device__ __forceinline__ float4 f4max(float4 a, float4 b) {
    return make_float4(fmaxf(a.x,b.x), fmaxf(a.y,b.y), fmaxf(a.z,b.z), fmaxf(a.w,b.w));
}
__device__ __forceinline__ float4 hmax4(float4 A, float4 B, float4 C) {
    float mB  = fmaxf(fmaxf(B.x,B.y), fmaxf(B.z,B.w));
    float azw = fmaxf(A.z, A.w);
    float cxy = fmaxf(C.x, C.y);
    float4 o;
    o.x = fmaxf(mB, fmaxf(A.y, azw));
    o.y = fmaxf(fmaxf(azw, mB), C.x);
    o.z = fmaxf(A.w, fmaxf(mB, cxy));
    o.w = fmaxf(mB, fmaxf(cxy, C.z));
    return o;
}

// Fully-fused split-half NMS, float4 shared-memory passes, 1024 threads.
__global__ __launch_bounds__(NMS_T) void nms_k(const float* __restrict__ scores) {
    extern __shared__ float sh[];
    float* S  = sh;
    float* MM = sh + NBUF;
    float* SS = sh + 2*NBUF;
    float* TP = sh + 3*NBUF;

    int tid = threadIdx.x;
    int tx = tid & 31;
    int ty = tid >> 5;
    int b   = blockIdx.z;
    int gx0 = blockIdx.x * CTX - HAL;
    int gy0 = blockIdx.y * CTY - HAL;
    int hlo = ((int)(blockIdx.y * CTY) < 256) ? 0 : 256;
    int hhi = hlo + 255;
    const float* sb = scores + b * HWSZ;

    for (int idx = tid; idx < NBUF; idx += NMS_T) {
        int br = idx / BW, bc = idx % BW;
        int gy = gy0 + br, gx = gx0 + bc;
        float v = -INFINITY;
        if (bc < 94 && gy >= hlo && gy <= hhi && gx >= 0 && gx < WW)
            v = sb[gy * WW + gx];
        S[idx] = v;
    }
    __syncthreads();

#define VPASS4(SRC, H)                                                         \
    {                                                                          \
        const int r1 = HAL + CTY + (H);                                        \
        const int c0 = (HAL - (H) - 3) & ~3;                                   \
        const int Gc = (HAL + CTX + (H) + 3 - c0 + 3) >> 2;                    \
        if (tx < Gc) {                                                         \
            int col = c0 + 4*tx;                                               \
            for (int r = HAL - (H) + ty; r < r1; r += 32) {                    \
                const float4* p = (const float4*)(SRC + (r-3)*BW + col);       \
                float4 m = p[0];                                               \
                m = f4max(m, p[24]);  m = f4max(m, p[48]);                     \
                m = f4max(m, p[72]);  m = f4max(m, p[96]);                     \
                m = f4max(m, p[120]); m = f4max(m, p[144]);                    \
                *(float4*)(TP + r*BW + col) = m;                               \
            }                                                                  \
        }                                                                      \
        __syncthreads();                                                       \
    }

#define HLOAD(g, r)                                                            \
    float4 A = *(const float4*)(TP + (r)*BW + (g) - 4);                        \
    float4 B = *(const float4*)(TP + (r)*BW + (g));                            \
    float4 C = *(const float4*)(TP + (r)*BW + (g) + 4);                        \
    float4 o = hmax4(A, B, C);

    VPASS4(S, 12)
    {
        const int o0c = 0, Go = (91 - o0c + 3) >> 2;
        if (tx < Go) {
            int g = o0c + 4*tx;
            int gxg = gx0 + g;
            for (int r = 3 + ty; r < 59; r += 32) {
                HLOAD(g, r)
                float4 sv = *(const float4*)(S + r*BW + g);
                int gy = gy0 + r;
                bool rok = (gy >= hlo) && (gy <= hhi);
                float4 mm;
                mm.x = (rok && (unsigned)(gxg+0) < 512u) ? ((sv.x==o.x)?1.f:0.f) : -INFINITY;
                mm.y = (rok && (unsigned)(gxg+1) < 512u) ? ((sv.y==o.y)?1.f:0.f) : -INFINITY;
                mm.z = (rok && (unsigned)(gxg+2) < 512u) ? ((sv.z==o.z)?1.f:0.f) : -INFINITY;
                mm.w = (rok && (unsigned)(gxg+3) < 512u) ? ((sv.w==o.w)?1.f:0.f) : -INFINITY;
                *(float4*)(MM + r*BW + g) = mm;
            }
        }
        __syncthreads();
    }

    VPASS4(MM, 9)
    {
        const int o0c = 4, Go = (88 - o0c + 3) >> 2;
        if (tx < Go) {
            int g = o0c + 4*tx;
            int gxg = gx0 + g;
            for (int r = 6 + ty; r < 56; r += 32) {
                HLOAD(g, r)
                float4 sv = *(const float4*)(S + r*BW + g);
                int gy = gy0 + r;
                bool rok = (gy >= hlo) && (gy <= hhi);
                float4 ss;
                ss.x = (rok && (unsigned)(gxg+0) < 512u) ? ((o.x>0.f)?-1.f:sv.x) : -INFINITY;
                ss.y = (rok && (unsigned)(gxg+1) < 512u) ? ((o.y>0.f)?-1.f:sv.y) : -INFINITY;
                ss.z = (rok && (unsigned)(gxg+2) < 512u) ? ((o.z>0.f)?-1.f:sv.z) : -INFINITY;
                ss.w = (rok && (unsigned)(gxg+3) < 512u) ? ((o.w>0.f)?-1.f:sv.w) : -INFINITY;
                *(float4*)(SS + r*BW + g) = ss;
            }
        }
        __syncthreads();
    }
    VPASS4(SS, 6)
    {
        const int o0c = 8, Go = (85 - o0c + 3) >> 2;
        if (tx < Go) {
            int g = o0c + 4*tx;
            for (int r = 9 + ty; r < 53; r += 32) {
                HLOAD(g, r)
                float4 ss = *(const float4*)(SS + r*BW + g);
                float4 mm = *(const float4*)(MM + r*BW + g);
                if (mm.x == 0.f && ss.x >= 0.f && ss.x == o.x) mm.x = 1.f;
                if (mm.y == 0.f && ss.y >= 0.f && ss.y == o.y) mm.y = 1.f;
                if (mm.z == 0.f && ss.z >= 0.f && ss.z == o.z) mm.z = 1.f;
                if (mm.w == 0.f && ss.w >= 0.f && ss.w == o.w) mm.w = 1.f;
                *(float4*)(MM + r*BW + g) = mm;
            }
        }
        __syncthreads();
    }

    VPASS4(MM, 3)
    {
        const int o0c = 12, Go = (82 - o0c + 3) >> 2;
        if (tx < Go) {
            int g = o0c + 4*tx;
            int gxg = gx0 + g;
            for (int r = 12 + ty; r < 50; r += 32) {
                HLOAD(g, r)
                float4 sv = *(const float4*)(S + r*BW + g);
                int gy = gy0 + r;
                bool rok = (gy >= hlo) && (gy <= hhi);
                float4 ss;
                ss.x = (rok && (unsigned)(gxg+0) < 512u) ? ((o.x>0.f)?-1.f:sv.x) : -INFINITY;
                ss.y = (rok && (unsigned)(gxg+1) < 512u) ? ((o.y>0.f)?-1.f:sv.y) : -INFINITY;
                ss.z = (rok && (unsigned)(gxg+2) < 512u) ? ((o.z>0.f)?-1.f:sv.z) : -INFINITY;
                ss.w = (rok && (unsigned)(gxg+3) < 512u) ? ((o.w>0.f)?-1.f:sv.w) : -INFINITY;
                *(float4*)(SS + r*BW + g) = ss;
            }
        }
        __syncthreads();
    }
    VPASS4(SS, 0)
    {
        const int o0c = 12, Go = (79 - o0c + 3) >> 2;
        if (tx < Go) {
            int g = o0c + 4*tx;
            for (int r = 15 + ty; r < 47; r += 32) {
                HLOAD(g, r)
                float4 ss = *(const float4*)(SS + r*BW + g);
                float4 mm = *(const float4*)(MM + r*BW + g);
                float4 sv = *(const float4*)(S  + r*BW + g);
                int gy = gy0 + r;
#define EMIT(OJ, MJ, SJ, VJ, J)                                                \
                {                                                              \
                    int bc = g + (J);                                          \
                    if (bc >= HAL && bc < HAL + CTX) {                         \
                        float mmv = MJ;                                        \
                        if (mmv == 0.f && SJ >= 0.f && SJ == OJ) mmv = 1.f;    \
                        int gx = gx0 + bc;                                     \
                        int rem = gy * WW + gx;                                \
                        bool border = (gy >= 3) && (gy < 510) &&               \
                                      (gx >= 3) && (gx < 510);                 \
                        float nms = (mmv > 0.f && border) ? VJ : 0.f;          \
                        if (nms > 0.f || rem < TOPK) {                         \
                            int pos = atomicAdd(&g_count[b], 1);               \
                            if (pos < CAP) {                                   \
                                unsigned long long key =                       \
                                    ((unsigned long long)__float_as_uint(nms) << 32) | \
                                    (unsigned long long)(0xFFFFFFFFu - (unsigned)rem); \
                                g_cand[b * CAP + pos] = key;                   \
                                int bin = min(NBINS-1, max(0, (int)(nms * (float)NBINS))); \
                                atomicAdd(&g_hist[b * NBINS + bin], 1);        \
                            }                                                  \
                        }                                                      \
                    }                                                          \
                }
                EMIT(o.x, mm.x, ss.x, sv.x, 0)
                EMIT(o.y, mm.y, ss.y, sv.y, 1)
                EMIT(o.z, mm.z, ss.z, sv.z, 2)
                EMIT(o.w, mm.w, ss.w, sv.w, 3)
            }
        }
    }
}

// per-batch: find threshold bin T (suffix >= TOPK), compact survivors, reset state
__global__ __launch_bounds__(1024) void thresh_compact_k() {
    int b = blockIdx.x;
    int t = threadIdx.x;
    __shared__ int gs[1024];
    __shared__ int sT;
    int base = NBINS - 1 - 4*t;
    int c0 = g_hist[b*NBINS + base];
    int c1 = g_hist[b*NBINS + base-1];
    int c2 = g_hist[b*NBINS + base-2];
    int c3 = g_hist[b*NBINS + base-3];
    int s = c0 + c1 + c2 + c3;
    gs[t] = s;
    g_hist[b*NBINS + base]   = 0;
    g_hist[b*NBINS + base-1] = 0;
    g_hist[b*NBINS + base-2] = 0;
    g_hist[b*NBINS + base-3] = 0;
    __syncthreads();
    for (int off = 1; off < 1024; off <<= 1) {
        int v = (t >= off) ? gs[t-off] : 0;
        __syncthreads();
        gs[t] += v;
        __syncthreads();
    }
    int total = gs[1023];
    int excl = gs[t] - s;
    if (excl < TOPK && excl + s >= TOPK) {
        int T = base - 3;
        int cum = excl + c0;
        if (cum >= TOPK) T = base;
        else { cum += c1; if (cum >= TOPK) T = base-1;
               else { cum += c2; if (cum >= TOPK) T = base-2; } }
        sT = T;
    }
    if (t == 0 && total < TOPK) sT = 0;
    __syncthreads();
    int T = sT;
    int cnt = min(g_count[b], CAP);
    for (int i = t; i < cnt; i += 1024) {
        unsigned long long key = g_cand[b*CAP + i];
        float v = __uint_as_float((unsigned)(key >> 32));
        int bin = min(NBINS-1, max(0, (int)(v * (float)NBINS)));
        if (bin >= T) {
            int p = atomicAdd(&g_scount[b], 1);
            if (p < MAXS) g_surv[b*MAXS + p] = key;
        }
    }
    __syncthreads();
    if (t == 0) g_count[b] = 0;
}

// 2D-parallel partial ranking + distributed per-row scatter epilogue.
// An i-chunk (row) is complete when all gridDim.x blocks with that y finished;
// the last contributor scatters it immediately (atomicExch reads+resets rank).
__global__ __launch_bounds__(256) void rank_scatter_k() {
    int b = blockIdx.z;
    int m = min(g_scount[b], MAXS);
    const unsigned long long* sv = g_surv + b*MAXS;
    __shared__ unsigned long long sk[256];
    __shared__ int sdone;
    for (int ib = blockIdx.y; ib * 256 < m; ib += gridDim.y) {
        int i = ib * 256 + threadIdx.x;
        unsigned long long mykey = (i < m) ? sv[i] : 0ull;
        int rank = 0;
        for (int jt = blockIdx.x; jt * 256 < m; jt += gridDim.x) {
            int j = jt * 256 + threadIdx.x;
            sk[threadIdx.x] = (j < m) ? sv[j] : 0ull;
            __syncthreads();
            int lim = min(256, m - jt * 256);
            if (i < m) {
                int u = 0;
                for (; u + 4 <= lim; u += 4) {
                    rank += (sk[u]   > mykey) ? 1 : 0;
                    rank += (sk[u+1] > mykey) ? 1 : 0;
                    rank += (sk[u+2] > mykey) ? 1 : 0;
                    rank += (sk[u+3] > mykey) ? 1 : 0;
                }
                for (; u < lim; ++u) rank += (sk[u] > mykey) ? 1 : 0;
            }
            __syncthreads();
        }
        if (i < m && rank) atomicAdd(&g_rank[b*MAXS + i], rank);
        __threadfence();
        __syncthreads();
        if (threadIdx.x == 0) {
            int v = atomicAdd(&g_rowdone[b*128 + ib], 1);
            sdone = (v == (int)gridDim.x - 1) ? 1 : 0;
        }
        __syncthreads();
        if (sdone) {
            if (i < m) {
                int r = atomicExch(&g_rank[b*MAXS + i], 0);   // read + replay-reset
                if (r < TOPK) {
                    int flatidx = (int)(0xFFFFFFFFu - (unsigned)(mykey & 0xFFFFFFFFull));
                    g_selidx[b * TOPK + r] = flatidx;
                }
            }
            if (threadIdx.x == 0) g_rowdone[b*128 + ib] = 0;
        }
        __syncthreads();
    }
}

__device__ __forceinline__ float bilin1(const float* base, float x, float y) {
    float x0f = floorf(x), y0f = floorf(y);
    float wx = x - x0f, wy = y - y0f;
    int x0 = min(max((int)x0f, 0), WW - 1);
    int x1 = min(max((int)x0f + 1, 0), WW - 1);
    int y0 = min(max((int)y0f, 0), HH - 1);
    int y1 = min(max((int)y0f + 1, 0), HH - 1);
    float v00 = base[y0 * WW + x0], v01 = base[y0 * WW + x1];
    float v10 = base[y1 * WW + x0], v11 = base[y1 * WW + x1];
    return v00 * (1.f - wx) * (1.f - wy) + v01 * wx * (1.f - wy)
         + v10 * (1.f - wx) * wy + v11 * wx * wy;
}

// fused: warp0 does 5x5 softmax refine; all 128 threads sample+normalize desc
__global__ __launch_bounds__(128) void refine_desc_k(const float* __restrict__ scores,
                                                     const float* __restrict__ dmap,
                                                     float* __restrict__ out) {
    int t = blockIdx.x;
    int c = threadIdx.x;
    int b = t >> 11;
    int w = c >> 5, lane = c & 31;
    __shared__ float sxy[2];

    if (t == 0 && c < BB) g_scount[c] = 0;

    if (w == 0) {
        int idx = g_selidx[t];
        int ky = idx >> 9, kx = idx & 511;
        const float* sb = scores + b * HWSZ;
        int p = lane;
        float dxf = 0.f, dyf = 0.f, v = 0.f;
        if (p < 25) {
            int dy = p / 5 - 2, dx = p % 5 - 2;
            dxf = (float)dx; dyf = (float)dy;
            int y = ky + dy, x = kx + dx;
            v = (y >= 0 && y < HH && x >= 0 && x < WW) ? sb[y * WW + x] : 0.0f;
        }
        float pv = (p < 25) ? v : -INFINITY;
#pragma unroll
        for (int o = 16; o > 0; o >>= 1) pv = fmaxf(pv, __shfl_xor_sync(0xFFFFFFFFu, pv, o));
        float e = (p < 25) ? expf((v - pv) * 10.0f) : 0.0f;
        float se = e, sxv = e * dxf, syv = e * dyf;
#pragma unroll
        for (int o = 16; o > 0; o >>= 1) {
            se  += __shfl_xor_sync(0xFFFFFFFFu, se, o);
            sxv += __shfl_xor_sync(0xFFFFFFFFu, sxv, o);
            syv += __shfl_xor_sync(0xFFFFFFFFu, syv, o);
        }
        float rx = sxv / se, ry = syv / se;
        float ddx = (dxf - rx) * 0.5f, ddy = (dyf - ry) * 0.5f;
        float dc = e * (ddx * ddx + ddy * ddy);
#pragma unroll
        for (int o = 16; o > 0; o >>= 1) dc += __shfl_xor_sync(0xFFFFFFFFu, dc, o);

        if (lane == 0) {
            float kxf = ((float)kx + rx) / 511.f * 2.f - 1.f;
            float kyf = ((float)ky + ry) / 511.f * 2.f - 1.f;
            out[KXY_OFF + t * 2 + 0] = kxf;
            out[KXY_OFF + t * 2 + 1] = kyf;
            out[DISP_OFF + t] = dc / se;
            float xs = (kxf + 1.f) * 0.5f * (WW - 1);
            float ys = (kyf + 1.f) * 0.5f * (HH - 1);
            out[SC_OFF + t] = bilin1(sb, xs, ys);
            sxy[0] = xs; sxy[1] = ys;
        }
    }
    __syncthreads();

    float x = sxy[0], y = sxy[1];
    float x0f = floorf(x), y0f = floorf(y);
    float wx = x - x0f, wy = y - y0f;
    int x0 = min(max((int)x0f, 0), WW - 1);
    int x1 = min(max((int)x0f + 1, 0), WW - 1);
    int y0 = min(max((int)y0f, 0), HH - 1);
    int y1 = min(max((int)y0f + 1, 0), HH - 1);
    const float* base = dmap + ((size_t)b * 128 + c) * HWSZ;
    float v00 = base[y0 * WW + x0], v01 = base[y0 * WW + x1];
    float v10 = base[y1 * WW + x0], v11 = base[y1 * WW + x1];
    float v = v00 * (1.f - wx) * (1.f - wy) + v01 * wx * (1.f - wy)
            + v10 * (1.f - wx) * wy + v11 * wx * wy;

    float sq = v * v;
#pragma unroll
    for (int o = 16; o > 0; o >>= 1) sq += __shfl_xor_sync(0xFFFFFFFFu, sq, o);
    __shared__ float wsum[4];
    if (lane == 0) wsum[w] = sq;
    __syncthreads();
    float tot = wsum[0] + wsum[1] + wsum[2] + wsum[3];
    float nrm = fmaxf(sqrtf(tot), 1e-12f);
    out[DESC_OFF + (size_t)t * 128 + c] = v / nrm;
}

extern "C" void kernel_launch(void* const* d_in, const int* in_sizes, int n_in,
                              void* d_out, int out_size) {
    const float* scores;
    const float* dmap;
    if (in_sizes[0] == NPIX) {
        scores = (const float*)d_in[0];
        dmap   = (const float*)d_in[1];
    } else {
        scores = (const float*)d_in[1];
        dmap   = (const float*)d_in[0];
    }
    float* out = (float*)d_out;

    static bool attr_done = false;
    if (!attr_done) {
        cudaFuncSetAttribute(nms_k, cudaFuncAttributeMaxDynamicSharedMemorySize,
                             (4 * NBUF + 64) * (int)sizeof(float));
        attr_done = true;
    }

    dim3 ng(WW / CTX, HH / CTY, BB);
    nms_k<<<ng, NMS_T, (4 * NBUF + 64) * sizeof(float)>>>(scores);

    thresh_compact_k<<<BB, 1024>>>();

    dim3 rg(8, 8, BB);
    rank_scatter_k<<<rg, 256>>>();

    refine_desc_k<<<NKP, 128>>>(scores, dmap, out);
}

// round 15
// speedup vs baseline: 1.2014x; 1.1199x over previous
#include <cuda_runtime.h>
#include <math.h>

#define HH 512
#define WW 512
#define BB 2
#define HWSZ (HH*WW)
#define NPIX (BB*HWSZ)
#define TOPK 2048
#define CAP 262144
#define NKP (BB*TOPK)
#define NBINS 4096
#define MAXS 32768
#define SELB 64

#define KXY_OFF  0
#define DESC_OFF (BB*TOPK*2)
#define SC_OFF   (DESC_OFF + BB*TOPK*128)
#define DISP_OFF (SC_OFF + BB*TOPK)

#define CTX 64
#define CTY 32
#define HAL 15
#define BW  96
#define BHT 62
#define NBUF (BHT*BW)
#define NMS_T 1024

__device__ unsigned long long g_cand[BB*CAP];
__device__ unsigned long long g_surv[BB*MAXS];
__device__ int g_count[BB];
__device__ int g_scount[BB];
__device__ int g_hist[BB*NBINS];
__device__ int g_rank[BB*MAXS];
__device__ int g_rowdone[BB*128];
__device__ int g_T[BB];
__device__ int g_phase[BB];
__device__ int g_cdone[BB];
__device__ int g_selidx[NKP];

__device__ __forceinline__ float4 f4max(float4 a, float4 b) {
    return make_float4(fmaxf(a.x,b.x), fmaxf(a.y,b.y), fmaxf(a.z,b.z), fmaxf(a.w,b.w));
}
__device__ __forceinline__ float4 hmax4(float4 A, float4 B, float4 C) {
    float mB  = fmaxf(fmaxf(B.x,B.y), fmaxf(B.z,B.w));
    float azw = fmaxf(A.z, A.w);
    float cxy = fmaxf(C.x, C.y);
    float4 o;
    o.x = fmaxf(mB, fmaxf(A.y, azw));
    o.y = fmaxf(fmaxf(azw, mB), C.x);
    o.z = fmaxf(A.w, fmaxf(mB, cxy));
    o.w = fmaxf(mB, fmaxf(cxy, C.z));
    return o;
}

// Fully-fused split-half NMS, float4 shared-memory passes, 1024 threads.
__global__ __launch_bounds__(NMS_T) void nms_k(const float* __restrict__ scores) {
    extern __shared__ float sh[];
    float* S  = sh;
    float* MM = sh + NBUF;
    float* SS = sh + 2*NBUF;
    float* TP = sh + 3*NBUF;

    int tid = threadIdx.x;
    int tx = tid & 31;
    int ty = tid >> 5;
    int b   = blockIdx.z;
    int gx0 = blockIdx.x * CTX - HAL;
    int gy0 = blockIdx.y * CTY - HAL;
    int hlo = ((int)(blockIdx.y * CTY) < 256) ? 0 : 256;
    int hhi = hlo + 255;
    const float* sb = scores + b * HWSZ;

    for (int idx = tid; idx < NBUF; idx += NMS_T) {
        int br = idx / BW, bc = idx % BW;
        int gy = gy0 + br, gx = gx0 + bc;
        float v = -INFINITY;
        if (bc < 94 && gy >= hlo && gy <= hhi && gx >= 0 && gx < WW)
            v = sb[gy * WW + gx];
        S[idx] = v;
    }
    __syncthreads();

#define VPASS4(SRC, H)                                                         \
    {                                                                          \
        const int r1 = HAL + CTY + (H);                                        \
        const int c0 = (HAL - (H) - 3) & ~3;                                   \
        const int Gc = (HAL + CTX + (H) + 3 - c0 + 3) >> 2;                    \
        if (tx < Gc) {                                                         \
            int col = c0 + 4*tx;                                               \
            for (int r = HAL - (H) + ty; r < r1; r += 32) {                    \
                const float4* p = (const float4*)(SRC + (r-3)*BW + col);       \
                float4 m = p[0];                                               \
                m = f4max(m, p[24]);  m = f4max(m, p[48]);                     \
                m = f4max(m, p[72]);  m = f4max(m, p[96]);                     \
                m = f4max(m, p[120]); m = f4max(m, p[144]);                    \
                *(float4*)(TP + r*BW + col) = m;                               \
            }                                                                  \
        }                                                                      \
        __syncthreads();                                                       \
    }

#define HLOAD(g, r)                                                            \
    float4 A = *(const float4*)(TP + (r)*BW + (g) - 4);                        \
    float4 B = *(const float4*)(TP + (r)*BW + (g));                            \
    float4 C = *(const float4*)(TP + (r)*BW + (g) + 4);                        \
    float4 o = hmax4(A, B, C);

    VPASS4(S, 12)
    {
        const int o0c = 0, Go = (91 - o0c + 3) >> 2;
        if (tx < Go) {
            int g = o0c + 4*tx;
            int gxg = gx0 + g;
            for (int r = 3 + ty; r < 59; r += 32) {
                HLOAD(g, r)
                float4 sv = *(const float4*)(S + r*BW + g);
                int gy = gy0 + r;
                bool rok = (gy >= hlo) && (gy <= hhi);
                float4 mm;
                mm.x = (rok && (unsigned)(gxg+0) < 512u) ? ((sv.x==o.x)?1.f:0.f) : -INFINITY;
                mm.y = (rok && (unsigned)(gxg+1) < 512u) ? ((sv.y==o.y)?1.f:0.f) : -INFINITY;
                mm.z = (rok && (unsigned)(gxg+2) < 512u) ? ((sv.z==o.z)?1.f:0.f) : -INFINITY;
                mm.w = (rok && (unsigned)(gxg+3) < 512u) ? ((sv.w==o.w)?1.f:0.f) : -INFINITY;
                *(float4*)(MM + r*BW + g) = mm;
            }
        }
        __syncthreads();
    }

    VPASS4(MM, 9)
    {
        const int o0c = 4, Go = (88 - o0c + 3) >> 2;
        if (tx < Go) {
            int g = o0c + 4*tx;
            int gxg = gx0 + g;
            for (int r = 6 + ty; r < 56; r += 32) {
                HLOAD(g, r)
                float4 sv = *(const float4*)(S + r*BW + g);
                int gy = gy0 + r;
                bool rok = (gy >= hlo) && (gy <= hhi);
                float4 ss;
                ss.x = (rok && (unsigned)(gxg+0) < 512u) ? ((o.x>0.f)?-1.f:sv.x) : -INFINITY;
                ss.y = (rok && (unsigned)(gxg+1) < 512u) ? ((o.y>0.f)?-1.f:sv.y) : -INFINITY;
                ss.z = (rok && (unsigned)(gxg+2) < 512u) ? ((o.z>0.f)?-1.f:sv.z) : -INFINITY;
                ss.w = (rok && (unsigned)(gxg+3) < 512u) ? ((o.w>0.f)?-1.f:sv.w) : -INFINITY;
                *(float4*)(SS + r*BW + g) = ss;
            }
        }
        __syncthreads();
    }
    VPASS4(SS, 6)
    {
        const int o0c = 8, Go = (85 - o0c + 3) >> 2;
        if (tx < Go) {
            int g = o0c + 4*tx;
            for (int r = 9 + ty; r < 53; r += 32) {
                HLOAD(g, r)
                float4 ss = *(const float4*)(SS + r*BW + g);
                float4 mm = *(const float4*)(MM + r*BW + g);
                if (mm.x == 0.f && ss.x >= 0.f && ss.x == o.x) mm.x = 1.f;
                if (mm.y == 0.f && ss.y >= 0.f && ss.y == o.y) mm.y = 1.f;
                if (mm.z == 0.f && ss.z >= 0.f && ss.z == o.z) mm.z = 1.f;
                if (mm.w == 0.f && ss.w >= 0.f && ss.w == o.w) mm.w = 1.f;
                *(float4*)(MM + r*BW + g) = mm;
            }
        }
        __syncthreads();
    }

    VPASS4(MM, 3)
    {
        const int o0c = 12, Go = (82 - o0c + 3) >> 2;
        if (tx < Go) {
            int g = o0c + 4*tx;
            int gxg = gx0 + g;
            for (int r = 12 + ty; r < 50; r += 32) {
                HLOAD(g, r)
                float4 sv = *(const float4*)(S + r*BW + g);
                int gy = gy0 + r;
                bool rok = (gy >= hlo) && (gy <= hhi);
                float4 ss;
                ss.x = (rok && (unsigned)(gxg+0) < 512u) ? ((o.x>0.f)?-1.f:sv.x) : -INFINITY;
                ss.y = (rok && (unsigned)(gxg+1) < 512u) ? ((o.y>0.f)?-1.f:sv.y) : -INFINITY;
                ss.z = (rok && (unsigned)(gxg+2) < 512u) ? ((o.z>0.f)?-1.f:sv.z) : -INFINITY;
                ss.w = (rok && (unsigned)(gxg+3) < 512u) ? ((o.w>0.f)?-1.f:sv.w) : -INFINITY;
                *(float4*)(SS + r*BW + g) = ss;
            }
        }
        __syncthreads();
    }
    VPASS4(SS, 0)
    {
        const int o0c = 12, Go = (79 - o0c + 3) >> 2;
        if (tx < Go) {
            int g = o0c + 4*tx;
            for (int r = 15 + ty; r < 47; r += 32) {
                HLOAD(g, r)
                float4 ss = *(const float4*)(SS + r*BW + g);
                float4 mm = *(const float4*)(MM + r*BW + g);
                float4 sv = *(const float4*)(S  + r*BW + g);
                int gy = gy0 + r;
#define EMIT(OJ, MJ, SJ, VJ, J)                                                \
                {                                                              \
                    int bc = g + (J);                                          \
                    if (bc >= HAL && bc < HAL + CTX) {                         \
                        float mmv = MJ;                                        \
                        if (mmv == 0.f && SJ >= 0.f && SJ == OJ) mmv = 1.f;    \
                        int gx = gx0 + bc;                                     \
                        int rem = gy * WW + gx;                                \
                        bool border = (gy >= 3) && (gy < 510) &&               \
                                      (gx >= 3) && (gx < 510);                 \
                        float nms = (mmv > 0.f && border) ? VJ : 0.f;          \
                        if (nms > 0.f || rem < TOPK) {                         \
                            int pos = atomicAdd(&g_count[b], 1);               \
                            if (pos < CAP) {                                   \
                                unsigned long long key =                       \
                                    ((unsigned long long)__float_as_uint(nms) << 32) | \
                                    (unsigned long long)(0xFFFFFFFFu - (unsigned)rem); \
                                g_cand[b * CAP + pos] = key;                   \
                                int bin = min(NBINS-1, max(0, (int)(nms * (float)NBINS))); \
                                atomicAdd(&g_hist[b * NBINS + bin], 1);        \
                            }                                                  \
                        }                                                      \
                    }                                                          \
                }
                EMIT(o.x, mm.x, ss.x, sv.x, 0)
                EMIT(o.y, mm.y, ss.y, sv.y, 1)
                EMIT(o.z, mm.z, ss.z, sv.z, 2)
                EMIT(o.w, mm.w, ss.w, sv.w, 3)
            }
        }
    }
}

// Merged selection: threshold scan -> compact -> rank -> scatter, one kernel.
// 64 blocks per batch (128 total), all resident -> device spin barriers safe.
__global__ __launch_bounds__(256) void select_k() {
    int b = blockIdx.y;
    int bid = blockIdx.x;         // 0..SELB-1
    int t = threadIdx.x;
    __shared__ int gs[256];
    __shared__ unsigned long long sk[256];
    __shared__ int sdone;

    // ---- phase 0: block 0 computes threshold T (and resets hist) ----
    if (bid == 0) {
        int base = NBINS - 1 - 16*t;
        int c[16]; int s = 0;
#pragma unroll
        for (int j = 0; j < 16; ++j) { c[j] = g_hist[b*NBINS + base - j]; s += c[j]; }
#pragma unroll
        for (int j = 0; j < 16; ++j) g_hist[b*NBINS + base - j] = 0;
        gs[t] = s;
        __syncthreads();
        for (int off = 1; off < 256; off <<= 1) {
            int v = (t >= off) ? gs[t-off] : 0;
            __syncthreads();
            gs[t] += v;
            __syncthreads();
        }
        int total = gs[255];
        int excl = gs[t] - s;
        if (excl < TOPK && excl + s >= TOPK) {
            int T = base - 15;
            int cum = excl;
#pragma unroll
            for (int j = 0; j < 16; ++j) {
                cum += c[j];
                if (cum >= TOPK) { T = base - j; break; }
            }
            g_T[b] = T;
        }
        if (t == 0 && total < TOPK) g_T[b] = 0;
        __syncthreads();
        __threadfence();
        if (t == 0) atomicExch(&g_phase[b], 1);
    } else {
        if (t == 0) { while (atomicAdd(&g_phase[b], 0) == 0) __nanosleep(64); }
        __syncthreads();
    }

    // ---- phase 1: parallel compaction of survivors ----
    int T = g_T[b];
    int cnt = min(g_count[b], CAP);
    for (int i = bid*256 + t; i < cnt; i += SELB*256) {
        unsigned long long key = g_cand[b*CAP + i];
        float v = __uint_as_float((unsigned)(key >> 32));
        int bin = min(NBINS-1, max(0, (int)(v * (float)NBINS)));
        if (bin >= T) {
            int p = atomicAdd(&g_scount[b], 1);
            if (p < MAXS) g_surv[b*MAXS + p] = key;
        }
    }
    __threadfence();
    __syncthreads();
    if (t == 0) {
        atomicAdd(&g_cdone[b], 1);
        while (atomicAdd(&g_cdone[b], 0) < SELB) __nanosleep(64);
    }
    __syncthreads();

    // ---- phase 2: 8x8 rank + distributed per-row scatter ----
    int jb = bid & 7, ibb = bid >> 3;
    int m = min(g_scount[b], MAXS);
    const unsigned long long* sv = g_surv + b*MAXS;
    for (int ib = ibb; ib * 256 < m; ib += 8) {
        int i = ib * 256 + t;
        unsigned long long mykey = (i < m) ? sv[i] : 0ull;
        int rank = 0;
        for (int jt = jb; jt * 256 < m; jt += 8) {
            int j = jt * 256 + t;
            sk[t] = (j < m) ? sv[j] : 0ull;
            __syncthreads();
            int lim = min(256, m - jt * 256);
            if (i < m) {
                int u = 0;
                for (; u + 4 <= lim; u += 4) {
                    rank += (sk[u]   > mykey) ? 1 : 0;
                    rank += (sk[u+1] > mykey) ? 1 : 0;
                    rank += (sk[u+2] > mykey) ? 1 : 0;
                    rank += (sk[u+3] > mykey) ? 1 : 0;
                }
                for (; u < lim; ++u) rank += (sk[u] > mykey) ? 1 : 0;
            }
            __syncthreads();
        }
        if (i < m && rank) atomicAdd(&g_rank[b*MAXS + i], rank);
        __threadfence();
        __syncthreads();
        if (t == 0) {
            int v = atomicAdd(&g_rowdone[b*128 + ib], 1);
            sdone = (v == 7) ? 1 : 0;
        }
        __syncthreads();
        if (sdone) {
            if (i < m) {
                int r = atomicExch(&g_rank[b*MAXS + i], 0);
                if (r < TOPK) {
                    int flatidx = (int)(0xFFFFFFFFu - (unsigned)(mykey & 0xFFFFFFFFull));
                    g_selidx[b * TOPK + r] = flatidx;
                }
            }
            if (t == 0) g_rowdone[b*128 + ib] = 0;
        }
        __syncthreads();
    }
}

__device__ __forceinline__ float bilin1(const float* base, float x, float y) {
    float x0f = floorf(x), y0f = floorf(y);
    float wx = x - x0f, wy = y - y0f;
    int x0 = min(max((int)x0f, 0), WW - 1);
    int x1 = min(max((int)x0f + 1, 0), WW - 1);
    int y0 = min(max((int)y0f, 0), HH - 1);
    int y1 = min(max((int)y0f + 1, 0), HH - 1);
    float v00 = base[y0 * WW + x0], v01 = base[y0 * WW + x1];
    float v10 = base[y1 * WW + x0], v11 = base[y1 * WW + x1];
    return v00 * (1.f - wx) * (1.f - wy) + v01 * wx * (1.f - wy)
         + v10 * (1.f - wx) * wy + v11 * wx * wy;
}

// fused: warp0 does 5x5 softmax refine; all 128 threads sample+normalize desc
__global__ __launch_bounds__(128) void refine_desc_k(const float* __restrict__ scores,
                                                     const float* __restrict__ dmap,
                                                     float* __restrict__ out) {
    int t = blockIdx.x;
    int c = threadIdx.x;
    int b = t >> 11;
    int w = c >> 5, lane = c & 31;
    __shared__ float sxy[2];

    // reset replay state (none of these are read by this kernel)
    if (t == 0 && c < BB) {
        g_scount[c] = 0; g_count[c] = 0; g_phase[c] = 0; g_cdone[c] = 0;
    }

    if (w == 0) {
        int idx = g_selidx[t];
        int ky = idx >> 9, kx = idx & 511;
        const float* sb = scores + b * HWSZ;
        int p = lane;
        float dxf = 0.f, dyf = 0.f, v = 0.f;
        if (p < 25) {
            int dy = p / 5 - 2, dx = p % 5 - 2;
            dxf = (float)dx; dyf = (float)dy;
            int y = ky + dy, x = kx + dx;
            v = (y >= 0 && y < HH && x >= 0 && x < WW) ? sb[y * WW + x] : 0.0f;
        }
        float pv = (p < 25) ? v : -INFINITY;
#pragma unroll
        for (int o = 16; o > 0; o >>= 1) pv = fmaxf(pv, __shfl_xor_sync(0xFFFFFFFFu, pv, o));
        float e = (p < 25) ? expf((v - pv) * 10.0f) : 0.0f;
        float se = e, sxv = e * dxf, syv = e * dyf;
#pragma unroll
        for (int o = 16; o > 0; o >>= 1) {
            se  += __shfl_xor_sync(0xFFFFFFFFu, se, o);
            sxv += __shfl_xor_sync(0xFFFFFFFFu, sxv, o);
            syv += __shfl_xor_sync(0xFFFFFFFFu, syv, o);
        }
        float rx = sxv / se, ry = syv / se;
        float ddx = (dxf - rx) * 0.5f, ddy = (dyf - ry) * 0.5f;
        float dc = e * (ddx * ddx + ddy * ddy);
#pragma unroll
        for (int o = 16; o > 0; o >>= 1) dc += __shfl_xor_sync(0xFFFFFFFFu, dc, o);

        if (lane == 0) {
            float kxf = ((float)kx + rx) / 511.f * 2.f - 1.f;
            float kyf = ((float)ky + ry) / 511.f * 2.f - 1.f;
            out[KXY_OFF + t * 2 + 0] = kxf;
            out[KXY_OFF + t * 2 + 1] = kyf;
            out[DISP_OFF + t] = dc / se;
            float xs = (kxf + 1.f) * 0.5f * (WW - 1);
            float ys = (kyf + 1.f) * 0.5f * (HH - 1);
            out[SC_OFF + t] = bilin1(sb, xs, ys);
            sxy[0] = xs; sxy[1] = ys;
        }
    }
    __syncthreads();

    float x = sxy[0], y = sxy[1];
    float x0f = floorf(x), y0f = floorf(y);
    float wx = x - x0f, wy = y - y0f;
    int x0 = min(max((int)x0f, 0), WW - 1);
    int x1 = min(max((int)x0f + 1, 0), WW - 1);
    int y0 = min(max((int)y0f, 0), HH - 1);
    int y1 = min(max((int)y0f + 1, 0), HH - 1);
    const float* base = dmap + ((size_t)b * 128 + c) * HWSZ;
    float v00 = base[y0 * WW + x0], v01 = base[y0 * WW + x1];
    float v10 = base[y1 * WW + x0], v11 = base[y1 * WW + x1];
    float v = v00 * (1.f - wx) * (1.f - wy) + v01 * wx * (1.f - wy)
            + v10 * (1.f - wx) * wy + v11 * wx * wy;

    float sq = v * v;
#pragma unroll
    for (int o = 16; o > 0; o >>= 1) sq += __shfl_xor_sync(0xFFFFFFFFu, sq, o);
    __shared__ float wsum[4];
    if (lane == 0) wsum[w] = sq;
    __syncthreads();
    float tot = wsum[0] + wsum[1] + wsum[2] + wsum[3];
    float nrm = fmaxf(sqrtf(tot), 1e-12f);
    out[DESC_OFF + (size_t)t * 128 + c] = v / nrm;
}

extern "C" void kernel_launch(void* const* d_in, const int* in_sizes, int n_in,
                              void* d_out, int out_size) {
    const float* scores;
    const float* dmap;
    if (in_sizes[0] == NPIX) {
        scores = (const float*)d_in[0];
        dmap   = (const float*)d_in[1];
    } else {
        scores = (const float*)d_in[1];
        dmap   = (const float*)d_in[0];
    }
    float* out = (float*)d_out;

    static bool attr_done = false;
    if (!attr_done) {
        cudaFuncSetAttribute(nms_k, cudaFuncAttributeMaxDynamicSharedMemorySize,
                             (4 * NBUF + 64) * (int)sizeof(float));
        attr_done = true;
    }

    dim3 ng(WW / CTX, HH / CTY, BB);
    nms_k<<<ng, NMS_T, (4 * NBUF + 64) * sizeof(float)>>>(scores);

    dim3 sg(SELB, BB);
    select_k<<<sg, 256>>>();

    refine_desc_k<<<NKP, 128>>>(scores, dmap, out);
}

// round 16
// speedup vs baseline: 1.2094x; 1.0066x over previous
#include <cuda_runtime.h>
#include <math.h>

#define HH 512
#define WW 512
#define BB 2
#define HWSZ (HH*WW)
#define NPIX (BB*HWSZ)
#define TOPK 2048
#define CAP 262144
#define NKP (BB*TOPK)
#define NBINS 4096
#define MAXS 32768
#define SELB 64

#define KXY_OFF  0
#define DESC_OFF (BB*TOPK*2)
#define SC_OFF   (DESC_OFF + BB*TOPK*128)
#define DISP_OFF (SC_OFF + BB*TOPK)

#define CTX 64
#define CTY 32
#define HAL 15
#define BW  96
#define BHT 62
#define NBUF (BHT*BW)
#define NMS_T 1024

__device__ unsigned long long g_cand[BB*CAP];
__device__ unsigned long long g_surv[BB*MAXS];
__device__ int g_count[BB];
__device__ int g_scount[BB];
__device__ int g_hist[BB*NBINS];
__device__ int g_rank[BB*MAXS];
__device__ int g_rowdone[BB*128];
__device__ int g_T[BB];
__device__ int g_phase[BB];
__device__ int g_cdone[BB];
__device__ int g_selidx[NKP];

__device__ __forceinline__ float4 f4max(float4 a, float4 b) {
    return make_float4(fmaxf(a.x,b.x), fmaxf(a.y,b.y), fmaxf(a.z,b.z), fmaxf(a.w,b.w));
}
__device__ __forceinline__ float4 hmax4(float4 A, float4 B, float4 C) {
    float mB  = fmaxf(fmaxf(B.x,B.y), fmaxf(B.z,B.w));
    float azw = fmaxf(A.z, A.w);
    float cxy = fmaxf(C.x, C.y);
    float4 o;
    o.x = fmaxf(mB, fmaxf(A.y, azw));
    o.y = fmaxf(fmaxf(azw, mB), C.x);
    o.z = fmaxf(A.w, fmaxf(mB, cxy));
    o.w = fmaxf(mB, fmaxf(cxy, C.z));
    return o;
}

// Fully-fused split-half NMS, float4 shared-memory passes, 1024 threads.
__global__ __launch_bounds__(NMS_T) void nms_k(const float* __restrict__ scores) {
    extern __shared__ float sh[];
    float* S  = sh;
    float* MM = sh + NBUF;
    float* SS = sh + 2*NBUF;
    float* TP = sh + 3*NBUF;

    int tid = threadIdx.x;
    int tx = tid & 31;
    int ty = tid >> 5;
    int b   = blockIdx.z;
    int gx0 = blockIdx.x * CTX - HAL;
    int gy0 = blockIdx.y * CTY - HAL;
    int hlo = ((int)(blockIdx.y * CTY) < 256) ? 0 : 256;
    int hhi = hlo + 255;
    const float* sb = scores + b * HWSZ;

    for (int idx = tid; idx < NBUF; idx += NMS_T) {
        int br = idx / BW, bc = idx % BW;
        int gy = gy0 + br, gx = gx0 + bc;
        float v = -INFINITY;
        if (bc < 94 && gy >= hlo && gy <= hhi && gx >= 0 && gx < WW)
            v = sb[gy * WW + gx];
        S[idx] = v;
    }
    __syncthreads();

#define VPASS4(SRC, H)                                                         \
    {                                                                          \
        const int r1 = HAL + CTY + (H);                                        \
        const int c0 = (HAL - (H) - 3) & ~3;                                   \
        const int Gc = (HAL + CTX + (H) + 3 - c0 + 3) >> 2;                    \
        if (tx < Gc) {                                                         \
            int col = c0 + 4*tx;                                               \
            for (int r = HAL - (H) + ty; r < r1; r += 32) {                    \
                const float4* p = (const float4*)(SRC + (r-3)*BW + col);       \
                float4 m = p[0];                                               \
                m = f4max(m, p[24]);  m = f4max(m, p[48]);                     \
                m = f4max(m, p[72]);  m = f4max(m, p[96]);                     \
                m = f4max(m, p[120]); m = f4max(m, p[144]);                    \
                *(float4*)(TP + r*BW + col) = m;                               \
            }                                                                  \
        }                                                                      \
        __syncthreads();                                                       \
    }

#define HLOAD(g, r)                                                            \
    float4 A = *(const float4*)(TP + (r)*BW + (g) - 4);                        \
    float4 B = *(const float4*)(TP + (r)*BW + (g));                            \
    float4 C = *(const float4*)(TP + (r)*BW + (g) + 4);                        \
    float4 o = hmax4(A, B, C);

    VPASS4(S, 12)
    {
        const int o0c = 0, Go = (91 - o0c + 3) >> 2;
        if (tx < Go) {
            int g = o0c + 4*tx;
            int gxg = gx0 + g;
            for (int r = 3 + ty; r < 59; r += 32) {
                HLOAD(g, r)
                float4 sv = *(const float4*)(S + r*BW + g);
                int gy = gy0 + r;
                bool rok = (gy >= hlo) && (gy <= hhi);
                float4 mm;
                mm.x = (rok && (unsigned)(gxg+0) < 512u) ? ((sv.x==o.x)?1.f:0.f) : -INFINITY;
                mm.y = (rok && (unsigned)(gxg+1) < 512u) ? ((sv.y==o.y)?1.f:0.f) : -INFINITY;
                mm.z = (rok && (unsigned)(gxg+2) < 512u) ? ((sv.z==o.z)?1.f:0.f) : -INFINITY;
                mm.w = (rok && (unsigned)(gxg+3) < 512u) ? ((sv.w==o.w)?1.f:0.f) : -INFINITY;
                *(float4*)(MM + r*BW + g) = mm;
            }
        }
        __syncthreads();
    }

    VPASS4(MM, 9)
    {
        const int o0c = 4, Go = (88 - o0c + 3) >> 2;
        if (tx < Go) {
            int g = o0c + 4*tx;
            int gxg = gx0 + g;
            for (int r = 6 + ty; r < 56; r += 32) {
                HLOAD(g, r)
                float4 sv = *(const float4*)(S + r*BW + g);
                int gy = gy0 + r;
                bool rok = (gy >= hlo) && (gy <= hhi);
                float4 ss;
                ss.x = (rok && (unsigned)(gxg+0) < 512u) ? ((o.x>0.f)?-1.f:sv.x) : -INFINITY;
                ss.y = (rok && (unsigned)(gxg+1) < 512u) ? ((o.y>0.f)?-1.f:sv.y) : -INFINITY;
                ss.z = (rok && (unsigned)(gxg+2) < 512u) ? ((o.z>0.f)?-1.f:sv.z) : -INFINITY;
                ss.w = (rok && (unsigned)(gxg+3) < 512u) ? ((o.w>0.f)?-1.f:sv.w) : -INFINITY;
                *(float4*)(SS + r*BW + g) = ss;
            }
        }
        __syncthreads();
    }
    VPASS4(SS, 6)
    {
        const int o0c = 8, Go = (85 - o0c + 3) >> 2;
        if (tx < Go) {
            int g = o0c + 4*tx;
            for (int r = 9 + ty; r < 53; r += 32) {
                HLOAD(g, r)
                float4 ss = *(const float4*)(SS + r*BW + g);
                float4 mm = *(const float4*)(MM + r*BW + g);
                if (mm.x == 0.f && ss.x >= 0.f && ss.x == o.x) mm.x = 1.f;
                if (mm.y == 0.f && ss.y >= 0.f && ss.y == o.y) mm.y = 1.f;
                if (mm.z == 0.f && ss.z >= 0.f && ss.z == o.z) mm.z = 1.f;
                if (mm.w == 0.f && ss.w >= 0.f && ss.w == o.w) mm.w = 1.f;
                *(float4*)(MM + r*BW + g) = mm;
            }
        }
        __syncthreads();
    }

    VPASS4(MM, 3)
    {
        const int o0c = 12, Go = (82 - o0c + 3) >> 2;
        if (tx < Go) {
            int g = o0c + 4*tx;
            int gxg = gx0 + g;
            for (int r = 12 + ty; r < 50; r += 32) {
                HLOAD(g, r)
                float4 sv = *(const float4*)(S + r*BW + g);
                int gy = gy0 + r;
                bool rok = (gy >= hlo) && (gy <= hhi);
                float4 ss;
                ss.x = (rok && (unsigned)(gxg+0) < 512u) ? ((o.x>0.f)?-1.f:sv.x) : -INFINITY;
                ss.y = (rok && (unsigned)(gxg+1) < 512u) ? ((o.y>0.f)?-1.f:sv.y) : -INFINITY;
                ss.z = (rok && (unsigned)(gxg+2) < 512u) ? ((o.z>0.f)?-1.f:sv.z) : -INFINITY;
                ss.w = (rok && (unsigned)(gxg+3) < 512u) ? ((o.w>0.f)?-1.f:sv.w) : -INFINITY;
                *(float4*)(SS + r*BW + g) = ss;
            }
        }
        __syncthreads();
    }
    VPASS4(SS, 0)
    {
        const int o0c = 12, Go = (79 - o0c + 3) >> 2;
        if (tx < Go) {
            int g = o0c + 4*tx;
            for (int r = 15 + ty; r < 47; r += 32) {
                HLOAD(g, r)
                float4 ss = *(const float4*)(SS + r*BW + g);
                float4 mm = *(const float4*)(MM + r*BW + g);
                float4 sv = *(const float4*)(S  + r*BW + g);
                int gy = gy0 + r;
#define EMIT(OJ, MJ, SJ, VJ, J)                                                \
                {                                                              \
                    int bc = g + (J);                                          \
                    if (bc >= HAL && bc < HAL + CTX) {                         \
                        float mmv = MJ;                                        \
                        if (mmv == 0.f && SJ >= 0.f && SJ == OJ) mmv = 1.f;    \
                        int gx = gx0 + bc;                                     \
                        int rem = gy * WW + gx;                                \
                        bool border = (gy >= 3) && (gy < 510) &&               \
                                      (gx >= 3) && (gx < 510);                 \
                        float nms = (mmv > 0.f && border) ? VJ : 0.f;          \
                        if (nms > 0.f || rem < TOPK) {                         \
                            int pos = atomicAdd(&g_count[b], 1);               \
                            if (pos < CAP) {                                   \
                                unsigned long long key =                       \
                                    ((unsigned long long)__float_as_uint(nms) << 32) | \
                                    (unsigned long long)(0xFFFFFFFFu - (unsigned)rem); \
                                g_cand[b * CAP + pos] = key;                   \
                                int bin = min(NBINS-1, max(0, (int)(nms * (float)NBINS))); \
                                atomicAdd(&g_hist[b * NBINS + bin], 1);        \
                            }                                                  \
                        }                                                      \
                    }                                                          \
                }
                EMIT(o.x, mm.x, ss.x, sv.x, 0)
                EMIT(o.y, mm.y, ss.y, sv.y, 1)
                EMIT(o.z, mm.z, ss.z, sv.z, 2)
                EMIT(o.w, mm.w, ss.w, sv.w, 3)
            }
        }
    }
}

// Merged selection: threshold scan -> compact -> rank -> scatter, one kernel.
// 64 blocks per batch (128 total), all resident -> device spin barriers safe.
__global__ __launch_bounds__(256) void select_k() {
    int b = blockIdx.y;
    int bid = blockIdx.x;         // 0..SELB-1
    int t = threadIdx.x;
    __shared__ int gs[256];
    __shared__ unsigned long long sk[256];
    __shared__ int sdone;

    // ---- phase 0: block 0 computes threshold T (and resets hist) ----
    if (bid == 0) {
        int base = NBINS - 1 - 16*t;
        int c[16]; int s = 0;
#pragma unroll
        for (int j = 0; j < 16; ++j) { c[j] = g_hist[b*NBINS + base - j]; s += c[j]; }
#pragma unroll
        for (int j = 0; j < 16; ++j) g_hist[b*NBINS + base - j] = 0;
        gs[t] = s;
        __syncthreads();
        for (int off = 1; off < 256; off <<= 1) {
            int v = (t >= off) ? gs[t-off] : 0;
            __syncthreads();
            gs[t] += v;
            __syncthreads();
        }
        int total = gs[255];
        int excl = gs[t] - s;
        if (excl < TOPK && excl + s >= TOPK) {
            int T = base - 15;
            int cum = excl;
#pragma unroll
            for (int j = 0; j < 16; ++j) {
                cum += c[j];
                if (cum >= TOPK) { T = base - j; break; }
            }
            g_T[b] = T;
        }
        if (t == 0 && total < TOPK) g_T[b] = 0;
        __syncthreads();
        __threadfence();
        if (t == 0) atomicExch(&g_phase[b], 1);
    } else {
        if (t == 0) { while (atomicAdd(&g_phase[b], 0) == 0) __nanosleep(64); }
        __syncthreads();
    }

    // ---- phase 1: parallel compaction of survivors ----
    int T = g_T[b];
    int cnt = min(g_count[b], CAP);
    for (int i = bid*256 + t; i < cnt; i += SELB*256) {
        unsigned long long key = g_cand[b*CAP + i];
        float v = __uint_as_float((unsigned)(key >> 32));
        int bin = min(NBINS-1, max(0, (int)(v * (float)NBINS)));
        if (bin >= T) {
            int p = atomicAdd(&g_scount[b], 1);
            if (p < MAXS) g_surv[b*MAXS + p] = key;
        }
    }
    __threadfence();
    __syncthreads();
    if (t == 0) {
        atomicAdd(&g_cdone[b], 1);
        while (atomicAdd(&g_cdone[b], 0) < SELB) __nanosleep(64);
    }
    __syncthreads();

    // ---- phase 2: 8x8 rank + distributed per-row scatter ----
    int jb = bid & 7, ibb = bid >> 3;
    int m = min(g_scount[b], MAXS);
    const unsigned long long* sv = g_surv + b*MAXS;
    for (int ib = ibb; ib * 256 < m; ib += 8) {
        int i = ib * 256 + t;
        unsigned long long mykey = (i < m) ? sv[i] : 0ull;
        int rank = 0;
        for (int jt = jb; jt * 256 < m; jt += 8) {
            int j = jt * 256 + t;
            sk[t] = (j < m) ? sv[j] : 0ull;
            __syncthreads();
            int lim = min(256, m - jt * 256);
            if (i < m) {
                int u = 0;
                for (; u + 4 <= lim; u += 4) {
                    rank += (sk[u]   > mykey) ? 1 : 0;
                    rank += (sk[u+1] > mykey) ? 1 : 0;
                    rank += (sk[u+2] > mykey) ? 1 : 0;
                    rank += (sk[u+3] > mykey) ? 1 : 0;
                }
                for (; u < lim; ++u) rank += (sk[u] > mykey) ? 1 : 0;
            }
            __syncthreads();
        }
        if (i < m && rank) atomicAdd(&g_rank[b*MAXS + i], rank);
        __threadfence();
        __syncthreads();
        if (t == 0) {
            int v = atomicAdd(&g_rowdone[b*128 + ib], 1);
            sdone = (v == 7) ? 1 : 0;
        }
        __syncthreads();
        if (sdone) {
            if (i < m) {
                int r = atomicExch(&g_rank[b*MAXS + i], 0);
                if (r < TOPK) {
                    int flatidx = (int)(0xFFFFFFFFu - (unsigned)(mykey & 0xFFFFFFFFull));
                    g_selidx[b * TOPK + r] = flatidx;
                }
            }
            if (t == 0) g_rowdone[b*128 + ib] = 0;
        }
        __syncthreads();
    }
}

__device__ __forceinline__ float bilin1(const float* base, float x, float y) {
    float x0f = floorf(x), y0f = floorf(y);
    float wx = x - x0f, wy = y - y0f;
    int x0 = min(max((int)x0f, 0), WW - 1);
    int x1 = min(max((int)x0f + 1, 0), WW - 1);
    int y0 = min(max((int)y0f, 0), HH - 1);
    int y1 = min(max((int)y0f + 1, 0), HH - 1);
    float v00 = base[y0 * WW + x0], v01 = base[y0 * WW + x1];
    float v10 = base[y1 * WW + x0], v11 = base[y1 * WW + x1];
    return v00 * (1.f - wx) * (1.f - wy) + v01 * wx * (1.f - wy)
         + v10 * (1.f - wx) * wy + v11 * wx * wy;
}

// fused: warp0 does 5x5 softmax refine; all 128 threads sample+normalize desc
__global__ __launch_bounds__(128) void refine_desc_k(const float* __restrict__ scores,
                                                     const float* __restrict__ dmap,
                                                     float* __restrict__ out) {
    int t = blockIdx.x;
    int c = threadIdx.x;
    int b = t >> 11;
    int w = c >> 5, lane = c & 31;
    __shared__ float sxy[2];

    // reset replay state (none of these are read by this kernel)
    if (t == 0 && c < BB) {
        g_scount[c] = 0; g_count[c] = 0; g_phase[c] = 0; g_cdone[c] = 0;
    }

    if (w == 0) {
        int idx = g_selidx[t];
        int ky = idx >> 9, kx = idx & 511;
        const float* sb = scores + b * HWSZ;
        int p = lane;
        float dxf = 0.f, dyf = 0.f, v = 0.f;
        if (p < 25) {
            int dy = p / 5 - 2, dx = p % 5 - 2;
            dxf = (float)dx; dyf = (float)dy;
            int y = ky + dy, x = kx + dx;
            v = (y >= 0 && y < HH && x >= 0 && x < WW) ? sb[y * WW + x] : 0.0f;
        }
        float pv = (p < 25) ? v : -INFINITY;
#pragma unroll
        for (int o = 16; o > 0; o >>= 1) pv = fmaxf(pv, __shfl_xor_sync(0xFFFFFFFFu, pv, o));
        float e = (p < 25) ? expf((v - pv) * 10.0f) : 0.0f;
        float se = e, sxv = e * dxf, syv = e * dyf;
#pragma unroll
        for (int o = 16; o > 0; o >>= 1) {
            se  += __shfl_xor_sync(0xFFFFFFFFu, se, o);
            sxv += __shfl_xor_sync(0xFFFFFFFFu, sxv, o);
            syv += __shfl_xor_sync(0xFFFFFFFFu, syv, o);
        }
        float rx = sxv / se, ry = syv / se;
        float ddx = (dxf - rx) * 0.5f, ddy = (dyf - ry) * 0.5f;
        float dc = e * (ddx * ddx + ddy * ddy);
#pragma unroll
        for (int o = 16; o > 0; o >>= 1) dc += __shfl_xor_sync(0xFFFFFFFFu, dc, o);

        if (lane == 0) {
            float kxf = ((float)kx + rx) / 511.f * 2.f - 1.f;
            float kyf = ((float)ky + ry) / 511.f * 2.f - 1.f;
            out[KXY_OFF + t * 2 + 0] = kxf;
            out[KXY_OFF + t * 2 + 1] = kyf;
            out[DISP_OFF + t] = dc / se;
            float xs = (kxf + 1.f) * 0.5f * (WW - 1);
            float ys = (kyf + 1.f) * 0.5f * (HH - 1);
            out[SC_OFF + t] = bilin1(sb, xs, ys);
            sxy[0] = xs; sxy[1] = ys;
        }
    }
    __syncthreads();

    float x = sxy[0], y = sxy[1];
    float x0f = floorf(x), y0f = floorf(y);
    float wx = x - x0f, wy = y - y0f;
    int x0 = min(max((int)x0f, 0), WW - 1);
    int x1 = min(max((int)x0f + 1, 0), WW - 1);
    int y0 = min(max((int)y0f, 0), HH - 1);
    int y1 = min(max((int)y0f + 1, 0), HH - 1);
    const float* base = dmap + ((size_t)b * 128 + c) * HWSZ;
    float v00 = base[y0 * WW + x0], v01 = base[y0 * WW + x1];
    float v10 = base[y1 * WW + x0], v11 = base[y1 * WW + x1];
    float v = v00 * (1.f - wx) * (1.f - wy) + v01 * wx * (1.f - wy)
            + v10 * (1.f - wx) * wy + v11 * wx * wy;

    float sq = v * v;
#pragma unroll
    for (int o = 16; o > 0; o >>= 1) sq += __shfl_xor_sync(0xFFFFFFFFu, sq, o);
    __shared__ float wsum[4];
    if (lane == 0) wsum[w] = sq;
    __syncthreads();
    float tot = wsum[0] + wsum[1] + wsum[2] + wsum[3];
    float nrm = fmaxf(sqrtf(tot), 1e-12f);
    out[DESC_OFF + (size_t)t * 128 + c] = v / nrm;
}

extern "C" void kernel_launch(void* const* d_in, const int* in_sizes, int n_in,
                              void* d_out, int out_size) {
    const float* scores;
    const float* dmap;
    if (in_sizes[0] == NPIX) {
        scores = (const float*)d_in[0];
        dmap   = (const float*)d_in[1];
    } else {
        scores = (const float*)d_in[1];
        dmap   = (const float*)d_in[0];
    }
    float* out = (float*)d_out;

    static bool attr_done = false;
    if (!attr_done) {
        cudaFuncSetAttribute(nms_k, cudaFuncAttributeMaxDynamicSharedMemorySize,
                             (4 * NBUF + 64) * (int)sizeof(float));
        attr_done = true;
    }

    dim3 ng(WW / CTX, HH / CTY, BB);
    nms_k<<<ng, NMS_T, (4 * NBUF + 64) * sizeof(float)>>>(scores);

    dim3 sg(SELB, BB);
    select_k<<<sg, 256>>>();

    refine_desc_k<<<NKP, 128>>>(scores, dmap, out);
}